// round 14
// baseline (speedup 1.0000x reference)
#include <cuda_runtime.h>
#include <cuda_bf16.h>
#include <cuda_fp16.h>
#include <math.h>
#include <stdint.h>

#define BATCH 4
#define S_LEN 1024
#define EMB   1024
#define NH    16
#define HD    64
#define NROWS (BATCH * S_LEN)

// ---------------- scratch (no allocations allowed) ----------------
__device__ uint32_t g_hf16[NROWS * 512];        // hidden fp16 pairs [m][kp]
__device__ uint32_t g_hbh [NROWS * 512];        // hidden bf16 hi    [m][kp]
__device__ uint32_t g_hbl [NROWS * 512];        // hidden bf16 lo    [m][kp]
__device__ uint32_t g_qvh [NROWS * 1024];       // Q|V fp16 pairs: [row][kp], Q kp<512, V kp>=512
__device__ uint32_t g_kh  [NROWS * 512];        // K quantized fp16 pairs [row][kp]
__device__ uint32_t g_oh  [NROWS * 512];        // attention out fp16 pairs [row][kp]
__device__ uint32_t g_wkh [EMB * 512];          // Wk bf16 hi, [n][kp]
__device__ uint32_t g_wkl [EMB * 512];          // Wk bf16 lo, [n][kp]
__device__ uint32_t g_wqv [2048 * 512];         // Wq|Wv fp16, [n][kp]
__device__ uint32_t g_wp  [EMB * 512];          // Wproj fp16, [n][kp]

// ---------------- helpers ----------------
__device__ __forceinline__ void mma16bf(float* d, const uint32_t* a, uint32_t b0, uint32_t b1) {
    asm volatile(
        "mma.sync.aligned.m16n8k16.row.col.f32.bf16.bf16.f32 "
        "{%0,%1,%2,%3}, {%4,%5,%6,%7}, {%8,%9}, {%0,%1,%2,%3};"
        : "+f"(d[0]), "+f"(d[1]), "+f"(d[2]), "+f"(d[3])
        : "r"(a[0]), "r"(a[1]), "r"(a[2]), "r"(a[3]), "r"(b0), "r"(b1));
}

__device__ __forceinline__ void mma16f(float* d, const uint32_t* a, uint32_t b0, uint32_t b1) {
    asm volatile(
        "mma.sync.aligned.m16n8k16.row.col.f32.f16.f16.f32 "
        "{%0,%1,%2,%3}, {%4,%5,%6,%7}, {%8,%9}, {%0,%1,%2,%3};"
        : "+f"(d[0]), "+f"(d[1]), "+f"(d[2]), "+f"(d[3])
        : "r"(a[0]), "r"(a[1]), "r"(a[2]), "r"(a[3]), "r"(b0), "r"(b1));
}

__device__ __forceinline__ void ldsm_x4(uint32_t* r, uint32_t addr) {
    asm volatile("ldmatrix.sync.aligned.m8n8.x4.shared.b16 {%0,%1,%2,%3}, [%4];"
        : "=r"(r[0]), "=r"(r[1]), "=r"(r[2]), "=r"(r[3]) : "r"(addr));
}

__device__ __forceinline__ void ldsm_x4_trans(uint32_t* r, uint32_t addr) {
    asm volatile("ldmatrix.sync.aligned.m8n8.x4.trans.shared.b16 {%0,%1,%2,%3}, [%4];"
        : "=r"(r[0]), "=r"(r[1]), "=r"(r[2]), "=r"(r[3]) : "r"(addr));
}

#define CP_ASYNC16(saddr, gptr) \
    asm volatile("cp.async.cg.shared.global [%0], [%1], 16;" \
        :: "r"(saddr), "l"(gptr) : "memory")
#define CP_COMMIT() asm volatile("cp.async.commit_group;" ::: "memory")
#define CP_WAIT0()  asm volatile("cp.async.wait_group 0;" ::: "memory")

__device__ __forceinline__ uint32_t pack_bf2(float x0, float x1) {
    __nv_bfloat162 p = __floats2bfloat162_rn(x0, x1);
    return *(uint32_t*)&p;
}

__device__ __forceinline__ uint32_t pack_h2(float x0, float x1) {
    __half2 p = __floats2half2_rn(x0, x1);
    return *(uint32_t*)&p;
}

__device__ __forceinline__ void split_bf(float x, float& h, float& l) {
    __nv_bfloat16 hb = __float2bfloat16_rn(x);
    h = __bfloat162float(hb);
    l = x - h;
}

__device__ __forceinline__ uint32_t kivi2(float v0, float v1, float ma) {
    float scale = ma * (1.0f / 1.5f);
    float safe = (scale == 0.0f) ? 1.0f : scale;
    float c0 = fminf(fmaxf(rintf(v0 / safe + 1.5f), 0.0f), 3.0f);
    float c1 = fminf(fmaxf(rintf(v1 / safe + 1.5f), 0.0f), 3.0f);
    return pack_h2((c0 - 1.5f) * scale, (c1 - 1.5f) * scale);
}

// ---------------- prep kernels ----------------
__global__ __launch_bounds__(256) void prep_hidden(
    const float* __restrict__ hid, uint32_t* __restrict__ hf,
    uint32_t* __restrict__ hh, uint32_t* __restrict__ hl)
{
    int idx = blockIdx.x * 256 + threadIdx.x;
    int kp = idx & 511;
    int m  = idx >> 9;
    float2 v = *(const float2*)(hid + (size_t)m * EMB + 2 * kp);
    hf[idx] = pack_h2(v.x, v.y);
    float h0, l0, h1, l1;
    split_bf(v.x, h0, l0);
    split_bf(v.y, h1, l1);
    hh[idx] = pack_bf2(h0, h1);
    hl[idx] = pack_bf2(l0, l1);
}

__global__ __launch_bounds__(256) void prep_weights(
    const float* __restrict__ wa, const float* __restrict__ wpj,
    uint32_t* __restrict__ wkh, uint32_t* __restrict__ wkl,
    uint32_t* __restrict__ wqv, uint32_t* __restrict__ wp)
{
    int bidx = blockIdx.x;
    if (bidx < 2048) {
        int idx = bidx * 256 + threadIdx.x;
        int n  = idx & 1023;
        int kp = idx >> 10;
        float x0 = wa[(size_t)(2 * kp)     * (3 * EMB) + EMB + n];
        float x1 = wa[(size_t)(2 * kp + 1) * (3 * EMB) + EMB + n];
        float h0, l0, h1, l1;
        split_bf(x0, h0, l0);
        split_bf(x1, h1, l1);
        wkh[(size_t)n * 512 + kp] = pack_bf2(h0, h1);
        wkl[(size_t)n * 512 + kp] = pack_bf2(l0, l1);
    } else if (bidx < 6144) {
        int idx = (bidx - 2048) * 256 + threadIdx.x;
        int n  = idx & 2047;
        int kp = idx >> 11;
        int col = n + ((n >= 1024) ? 1024 : 0);
        float x0 = wa[(size_t)(2 * kp)     * (3 * EMB) + col];
        float x1 = wa[(size_t)(2 * kp + 1) * (3 * EMB) + col];
        wqv[(size_t)n * 512 + kp] = pack_h2(x0, x1);
    } else {
        int idx = (bidx - 6144) * 256 + threadIdx.x;
        int n  = idx & 1023;
        int kp = idx >> 10;
        float x0 = wpj[(size_t)(2 * kp)     * EMB + n];
        float x1 = wpj[(size_t)(2 * kp + 1) * EMB + n];
        wp[(size_t)n * 512 + kp] = pack_h2(x0, x1);
    }
}

// ---------------- fp16 GEMM: cp.async double-buffered, BK=32 ----------------
#define GF_S 20
#define GF_BUF (128 * GF_S)

__global__ __launch_bounds__(256, 2) void gemm_f16(
    const uint32_t* __restrict__ Apk, const uint32_t* __restrict__ Bp,
    const float* __restrict__ bias, float* __restrict__ C,
    uint32_t* __restrict__ Cp, int ldc, int K, int nsplit, int gap, int pack_out)
{
    __shared__ uint32_t As[2][GF_BUF];
    __shared__ uint32_t Bs[2][GF_BUF];

    const int tid = threadIdx.x;
    const int bx = blockIdx.x, by = blockIdx.y;
    const int bcol = bx * 128 + ((bx >= nsplit) ? gap : 0);
    const int lane = tid & 31, wid = tid >> 5;
    const int g = lane >> 2, tg = lane & 3;
    const int wm = (wid >> 2) * 64, wn = (wid & 3) * 32;

    const int la_row = lane & 15, la_chunk = (lane >> 4) * 4;

    const uint32_t as_base = (uint32_t)__cvta_generic_to_shared(As);
    const uint32_t bs_base = (uint32_t)__cvta_generic_to_shared(Bs);

    const int arow = tid >> 1, akp = (tid & 1) * 8;
    const uint32_t* App = Apk + (size_t)(by * 128 + arow) * 512 + akp;
    const uint32_t* Bpp = Bp  + (size_t)(bx * 128 + arow) * 512 + akp;

    auto load_tile = [&](int t, int bb) {
        const uint32_t da = as_base + (bb * GF_BUF + arow * GF_S + akp) * 4;
        const uint32_t db = bs_base + (bb * GF_BUF + arow * GF_S + akp) * 4;
        CP_ASYNC16(da,      App + t * 16);
        CP_ASYNC16(da + 16, App + t * 16 + 4);
        CP_ASYNC16(db,      Bpp + t * 16);
        CP_ASYNC16(db + 16, Bpp + t * 16 + 4);
    };

    float acc[4][4][4];
    #pragma unroll
    for (int mt = 0; mt < 4; mt++)
        #pragma unroll
        for (int nt = 0; nt < 4; nt++)
            #pragma unroll
            for (int i = 0; i < 4; i++) acc[mt][nt][i] = 0.0f;

    load_tile(0, 0);
    CP_COMMIT();
    CP_WAIT0();
    __syncthreads();

    const int ntiles = K >> 5;
    int buf = 0;
    for (int t = 0; t < ntiles; ++t) {
        if (t + 1 < ntiles) {
            load_tile(t + 1, buf ^ 1);
            CP_COMMIT();
        }

        const uint32_t as0 = as_base + (buf * GF_BUF) * 4;
        const uint32_t bs0 = bs_base + (buf * GF_BUF) * 4;

        #pragma unroll
        for (int ks = 0; ks < 2; ++ks) {
            const int kb = ks * 8;
            uint32_t af[4][4], bq[2][4];
            #pragma unroll
            for (int mt = 0; mt < 4; mt++)
                ldsm_x4(af[mt], as0 + ((wm + mt * 16 + la_row) * GF_S + kb + la_chunk) * 4);
            #pragma unroll
            for (int np = 0; np < 2; np++)
                ldsm_x4(bq[np], bs0 + ((wn + np * 16 + la_row) * GF_S + kb + la_chunk) * 4);
            #pragma unroll
            for (int mt = 0; mt < 4; mt++)
                #pragma unroll
                for (int np = 0; np < 2; np++) {
                    mma16f(acc[mt][2 * np + 0], af[mt], bq[np][0], bq[np][2]);
                    mma16f(acc[mt][2 * np + 1], af[mt], bq[np][1], bq[np][3]);
                }
        }

        if (t + 1 < ntiles) CP_WAIT0();
        __syncthreads();
        buf ^= 1;
    }

    #pragma unroll
    for (int mt = 0; mt < 4; mt++) {
        #pragma unroll
        for (int nt = 0; nt < 4; nt++) {
            const int col = bcol + wn + nt * 8 + 2 * tg;
            const float bv0 = bias[col], bv1 = bias[col + 1];
            const int row0 = by * 128 + wm + mt * 16 + g;
            float o00 = acc[mt][nt][0] + bv0, o01 = acc[mt][nt][1] + bv1;
            float o10 = acc[mt][nt][2] + bv0, o11 = acc[mt][nt][3] + bv1;
            if (pack_out) {
                const int kp = (col >= 2048) ? (512 + ((col - 2048) >> 1)) : (col >> 1);
                Cp[(size_t)row0 * 1024 + kp]       = pack_h2(o00, o01);
                Cp[(size_t)(row0 + 8) * 1024 + kp] = pack_h2(o10, o11);
            } else {
                *(float2*)(C + (size_t)row0 * ldc + col)       = make_float2(o00, o01);
                *(float2*)(C + (size_t)(row0 + 8) * ldc + col) = make_float2(o10, o11);
            }
        }
    }
}

// ---------------- bf16x3 GEMM for K: cp.async, BK=32, fused KIVI quant ----------------
#define G3_S 20
#define G3_BUF (128 * G3_S)
#define G3_SMEM_BYTES (8 * G3_BUF * 4)   // 4 planes x 2 buffers

__global__ __launch_bounds__(256, 2) void gemm_bf16k(
    const uint32_t* __restrict__ Ahg, const uint32_t* __restrict__ Alg,
    const uint32_t* __restrict__ Bhg, const uint32_t* __restrict__ Blg,
    const float* __restrict__ bias, uint32_t* __restrict__ Kp, int K)
{
    extern __shared__ uint32_t s3[];
    uint32_t* Ah = s3;                    // [2][G3_BUF]
    uint32_t* Al = Ah + 2 * G3_BUF;
    uint32_t* Bh = Al + 2 * G3_BUF;
    uint32_t* Bl = Bh + 2 * G3_BUF;

    const int tid = threadIdx.x;
    const int bx = blockIdx.x, by = blockIdx.y;
    const int lane = tid & 31, wid = tid >> 5;
    const int g = lane >> 2, tg = lane & 3;
    const int wm = (wid >> 2) * 64, wn = (wid & 3) * 32;

    const int la_row = lane & 15, la_chunk = (lane >> 4) * 4;

    const uint32_t ah_base = (uint32_t)__cvta_generic_to_shared(Ah);
    const uint32_t al_base = (uint32_t)__cvta_generic_to_shared(Al);
    const uint32_t bh_base = (uint32_t)__cvta_generic_to_shared(Bh);
    const uint32_t bl_base = (uint32_t)__cvta_generic_to_shared(Bl);

    const int arow = tid >> 1, akp = (tid & 1) * 8;
    const uint32_t* Ahp = Ahg + (size_t)(by * 128 + arow) * 512 + akp;
    const uint32_t* Alp = Alg + (size_t)(by * 128 + arow) * 512 + akp;
    const uint32_t* Bhp = Bhg + (size_t)(bx * 128 + arow) * 512 + akp;
    const uint32_t* Blp = Blg + (size_t)(bx * 128 + arow) * 512 + akp;

    auto load_tile = [&](int t, int bb) {
        const uint32_t off = (bb * G3_BUF + arow * G3_S + akp) * 4;
        CP_ASYNC16(ah_base + off,      Ahp + t * 16);
        CP_ASYNC16(ah_base + off + 16, Ahp + t * 16 + 4);
        CP_ASYNC16(al_base + off,      Alp + t * 16);
        CP_ASYNC16(al_base + off + 16, Alp + t * 16 + 4);
        CP_ASYNC16(bh_base + off,      Bhp + t * 16);
        CP_ASYNC16(bh_base + off + 16, Bhp + t * 16 + 4);
        CP_ASYNC16(bl_base + off,      Blp + t * 16);
        CP_ASYNC16(bl_base + off + 16, Blp + t * 16 + 4);
    };

    float acc[4][4][4];
    #pragma unroll
    for (int mt = 0; mt < 4; mt++)
        #pragma unroll
        for (int nt = 0; nt < 4; nt++)
            #pragma unroll
            for (int i = 0; i < 4; i++) acc[mt][nt][i] = 0.0f;

    load_tile(0, 0);
    CP_COMMIT();
    CP_WAIT0();
    __syncthreads();

    const int ntiles = K >> 5;
    int buf = 0;
    for (int t = 0; t < ntiles; ++t) {
        if (t + 1 < ntiles) {
            load_tile(t + 1, buf ^ 1);
            CP_COMMIT();
        }

        const uint32_t ah0 = ah_base + (buf * G3_BUF) * 4;
        const uint32_t al0 = al_base + (buf * G3_BUF) * 4;
        const uint32_t bh0 = bh_base + (buf * G3_BUF) * 4;
        const uint32_t bl0 = bl_base + (buf * G3_BUF) * 4;

        #pragma unroll
        for (int ks = 0; ks < 2; ++ks) {
            const int kb = ks * 8;
            uint32_t afh[4][4], afl[4][4], bqh[2][4], bql[2][4];
            #pragma unroll
            for (int mt = 0; mt < 4; mt++) {
                const uint32_t off = ((wm + mt * 16 + la_row) * G3_S + kb + la_chunk) * 4;
                ldsm_x4(afh[mt], ah0 + off);
                ldsm_x4(afl[mt], al0 + off);
            }
            #pragma unroll
            for (int np = 0; np < 2; np++) {
                const uint32_t off = ((wn + np * 16 + la_row) * G3_S + kb + la_chunk) * 4;
                ldsm_x4(bqh[np], bh0 + off);
                ldsm_x4(bql[np], bl0 + off);
            }
            #pragma unroll
            for (int mt = 0; mt < 4; mt++)
                #pragma unroll
                for (int np = 0; np < 2; np++) {
                    float* a0 = acc[mt][2 * np + 0];
                    float* a1 = acc[mt][2 * np + 1];
                    mma16bf(a0, afh[mt], bqh[np][0], bqh[np][2]);
                    mma16bf(a0, afh[mt], bql[np][0], bql[np][2]);
                    mma16bf(a0, afl[mt], bqh[np][0], bqh[np][2]);
                    mma16bf(a1, afh[mt], bqh[np][1], bqh[np][3]);
                    mma16bf(a1, afh[mt], bql[np][1], bql[np][3]);
                    mma16bf(a1, afl[mt], bqh[np][1], bqh[np][3]);
                }
        }

        if (t + 1 < ntiles) CP_WAIT0();
        __syncthreads();
        buf ^= 1;
    }

    // ---- epilogue: bias + KIVI 2-bit quant (group = tg-pair) + pack fp16 ----
    #pragma unroll
    for (int mt = 0; mt < 4; mt++) {
        #pragma unroll
        for (int nt = 0; nt < 4; nt++) {
            const int col = bx * 128 + wn + nt * 8 + 2 * tg;
            const float bv0 = bias[col], bv1 = bias[col + 1];
            const int row0 = by * 128 + wm + mt * 16 + g;
            float v00 = acc[mt][nt][0] + bv0, v01 = acc[mt][nt][1] + bv1;
            float v10 = acc[mt][nt][2] + bv0, v11 = acc[mt][nt][3] + bv1;
            float ma0 = fmaxf(fabsf(v00), fabsf(v01));
            float ma1 = fmaxf(fabsf(v10), fabsf(v11));
            ma0 = fmaxf(ma0, __shfl_xor_sync(0xffffffffu, ma0, 1));
            ma1 = fmaxf(ma1, __shfl_xor_sync(0xffffffffu, ma1, 1));
            const int kp = col >> 1;
            Kp[(size_t)row0 * 512 + kp]       = kivi2(v00, v01, ma0);
            Kp[(size_t)(row0 + 8) * 512 + kp] = kivi2(v10, v11, ma1);
        }
    }
}

// ---------------- Flash attention: cp.async double-buffered KV pipeline ----------------
#define SQH 36
#define ATT_FLOATS (128 * SQH + 2 * 64 * SQH + 128 * SQH + 2 * 64 * SQH + 2 * 64)

__global__ __launch_bounds__(256, 2) void attn_f16(
    const uint32_t* __restrict__ qvh, const uint32_t* __restrict__ kh,
    const float* __restrict__ mask, uint32_t* __restrict__ outp)
{
    extern __shared__ uint32_t smu[];
    uint32_t* Qs = smu;                       // [128][36]
    uint32_t* Ks = Qs + 128 * SQH;            // [2][64][36]
    uint32_t* Ps = Ks + 2 * 64 * SQH;         // [128][36]
    uint32_t* Vs = Ps + 128 * SQH;            // [2][64][36]
    float*    Ms = (float*)(Vs + 2 * 64 * SQH);  // [2][64]

    const int tid = threadIdx.x, lane = tid & 31, wid = tid >> 5;
    const int g = lane >> 2, tg = lane & 3;
    const int m0 = wid * 16;

    const int la_row = lane & 15, la_chunk = (lane >> 4) * 4;

    const uint32_t qs_base = (uint32_t)__cvta_generic_to_shared(Qs);
    const uint32_t ks_base = (uint32_t)__cvta_generic_to_shared(Ks);
    const uint32_t ps_base = (uint32_t)__cvta_generic_to_shared(Ps);
    const uint32_t vs_base = (uint32_t)__cvta_generic_to_shared(Vs);
    const uint32_t ms_base = (uint32_t)__cvta_generic_to_shared(Ms);

    const int bid = blockIdx.x;
    const int qt = bid & 7;
    const int h  = (bid >> 3) & 15;
    const int b  = bid >> 7;

    const uint32_t* qp = qvh + ((size_t)(b * S_LEN) + qt * 128) * 1024 + h * 32;
    const uint32_t* vp = qvh + ((size_t)(b * S_LEN)) * 1024 + 512 + h * 32;
    const uint32_t* kp = kh  + ((size_t)(b * S_LEN)) * 512 + h * 32;
    const float*    mp = mask + b * S_LEN;

    auto load_tile = [&](int ktn, int bb) {
        #pragma unroll
        for (int i = 0; i < 2; i++) {
            int f = tid + 256 * i;
            int row = f >> 3, w4 = (f & 7) * 4;
            int key = (ktn << 6) + row;
            CP_ASYNC16(ks_base + ((bb * 64 + row) * SQH + w4) * 4,
                       kp + (size_t)key * 512 + w4);
            CP_ASYNC16(vs_base + ((bb * 64 + row) * SQH + w4) * 4,
                       vp + (size_t)key * 1024 + w4);
        }
        if (tid < 16)
            CP_ASYNC16(ms_base + (bb * 64 + tid * 4) * 4, mp + (ktn << 6) + tid * 4);
    };

    load_tile(0, 0);
    CP_COMMIT();
    #pragma unroll
    for (int i = 0; i < 4; i++) {
        int f = tid + 256 * i;
        int row = f >> 3, w4 = (f & 7) * 4;
        uint4 u = *(const uint4*)(qp + (size_t)row * 1024 + w4);
        *(uint4*)&Qs[row * SQH + w4] = u;
    }

    float m_i[2] = {-INFINITY, -INFINITY}, l_i[2] = {0.0f, 0.0f};
    float oa[8][4];
    #pragma unroll
    for (int nt = 0; nt < 8; nt++)
        #pragma unroll
        for (int i = 0; i < 4; i++) oa[nt][i] = 0.0f;

    CP_WAIT0();
    __syncthreads();

    int buf = 0;
    const int NT = S_LEN / 64;
    for (int kt = 0; kt < NT; ++kt) {
        if (kt + 1 < NT) {
            load_tile(kt + 1, buf ^ 1);
            CP_COMMIT();
        }

        const uint32_t ksb = ks_base + (buf * 64 * SQH) * 4;
        const uint32_t vsb = vs_base + (buf * 64 * SQH) * 4;
        const float*   msb = Ms + buf * 64;

        // ---- S = Q K^T ----
        float sacc[8][4];
        #pragma unroll
        for (int nt = 0; nt < 8; nt++)
            #pragma unroll
            for (int i = 0; i < 4; i++) sacc[nt][i] = 0.0f;

        #pragma unroll
        for (int ks = 0; ks < 4; ++ks) {
            const int kb = ks * 8;
            uint32_t af[4];
            ldsm_x4(af, qs_base + ((m0 + la_row) * SQH + kb + la_chunk) * 4);
            #pragma unroll
            for (int np = 0; np < 4; ++np) {
                uint32_t bq[4];
                ldsm_x4(bq, ksb + ((np * 16 + la_row) * SQH + kb + la_chunk) * 4);
                mma16f(sacc[2 * np + 0], af, bq[0], bq[2]);
                mma16f(sacc[2 * np + 1], af, bq[1], bq[3]);
            }
        }

        // ---- online softmax ----
        #pragma unroll
        for (int rr = 0; rr < 2; ++rr) {
            float mx = -INFINITY;
            #pragma unroll
            for (int nt = 0; nt < 8; nt++) {
                const int c0 = nt * 8 + 2 * tg;
                float s0 = (sacc[nt][rr * 2 + 0] + msb[c0]) * 0.125f;
                float s1 = (sacc[nt][rr * 2 + 1] + msb[c0 + 1]) * 0.125f;
                sacc[nt][rr * 2 + 0] = s0;
                sacc[nt][rr * 2 + 1] = s1;
                mx = fmaxf(mx, fmaxf(s0, s1));
            }
            mx = fmaxf(mx, __shfl_xor_sync(0xffffffffu, mx, 1));
            mx = fmaxf(mx, __shfl_xor_sync(0xffffffffu, mx, 2));
            const float mnew = fmaxf(m_i[rr], mx);
            const float alpha = __expf(m_i[rr] - mnew);
            float rs = 0.0f;
            const int row = m0 + g + rr * 8;
            #pragma unroll
            for (int nt = 0; nt < 8; nt++) {
                float p0 = __expf(sacc[nt][rr * 2 + 0] - mnew);
                float p1 = __expf(sacc[nt][rr * 2 + 1] - mnew);
                rs += p0 + p1;
                Ps[row * SQH + nt * 4 + tg] = pack_h2(p0, p1);
            }
            rs += __shfl_xor_sync(0xffffffffu, rs, 1);
            rs += __shfl_xor_sync(0xffffffffu, rs, 2);
            l_i[rr] = l_i[rr] * alpha + rs;
            m_i[rr] = mnew;
            #pragma unroll
            for (int nt = 0; nt < 8; nt++) {
                oa[nt][rr * 2 + 0] *= alpha;
                oa[nt][rr * 2 + 1] *= alpha;
            }
        }
        __syncwarp();   // P rows are warp-private

        // ---- O += P V ----
        #pragma unroll
        for (int ks = 0; ks < 4; ++ks) {
            const int kb = ks * 8;
            uint32_t ap[4];
            ldsm_x4(ap, ps_base + ((m0 + la_row) * SQH + kb + la_chunk) * 4);
            #pragma unroll
            for (int np = 0; np < 4; ++np) {
                uint32_t bv[4];
                ldsm_x4_trans(bv, vsb +
                    ((ks * 16 + la_row) * SQH + (2 * np + (lane >> 4)) * 4) * 4);
                mma16f(oa[2 * np + 0], ap, bv[0], bv[1]);
                mma16f(oa[2 * np + 1], ap, bv[2], bv[3]);
            }
        }

        if (kt + 1 < NT) CP_WAIT0();
        __syncthreads();
        buf ^= 1;
    }

    // ---- epilogue: packed fp16 output [row][kp] for the proj GEMM ----
    #pragma unroll
    for (int rr = 0; rr < 2; ++rr) {
        const float inv = 1.0f / l_i[rr];
        const int srow = qt * 128 + m0 + g + rr * 8;
        uint32_t* op = outp + ((size_t)(b * S_LEN + srow)) * 512 + h * 32;
        #pragma unroll
        for (int nt = 0; nt < 8; nt++)
            op[nt * 4 + tg] = pack_h2(oa[nt][rr * 2 + 0] * inv, oa[nt][rr * 2 + 1] * inv);
    }
}

// ---------------- launch ----------------
extern "C" void kernel_launch(void* const* d_in, const int* in_sizes, int n_in,
                              void* d_out, int out_size)
{
    const float* hidden = (const float*)d_in[0];
    const float* mask   = (const float*)d_in[1];
    const float* w_attn = (const float*)d_in[2];
    const float* b_attn = (const float*)d_in[3];
    const float* w_proj = (const float*)d_in[4];
    const float* b_proj = (const float*)d_in[5];
    float* out = (float*)d_out;

    uint32_t *hf16, *hbh, *hbl, *qvh, *kh, *oh, *wkh, *wkl, *wqv, *wp;
    cudaGetSymbolAddress((void**)&hf16, g_hf16);
    cudaGetSymbolAddress((void**)&hbh,  g_hbh);
    cudaGetSymbolAddress((void**)&hbl,  g_hbl);
    cudaGetSymbolAddress((void**)&qvh,  g_qvh);
    cudaGetSymbolAddress((void**)&kh,   g_kh);
    cudaGetSymbolAddress((void**)&oh,   g_oh);
    cudaGetSymbolAddress((void**)&wkh,  g_wkh);
    cudaGetSymbolAddress((void**)&wkl,  g_wkl);
    cudaGetSymbolAddress((void**)&wqv,  g_wqv);
    cudaGetSymbolAddress((void**)&wp,   g_wp);

    const int att_smem = ATT_FLOATS * (int)sizeof(float);
    cudaFuncSetAttribute(attn_f16,
                         cudaFuncAttributeMaxDynamicSharedMemorySize, att_smem);
    cudaFuncSetAttribute(gemm_bf16k,
                         cudaFuncAttributeMaxDynamicSharedMemorySize, G3_SMEM_BYTES);

    // 0) prep: activations + fused weight packing
    prep_hidden<<<NROWS * 512 / 256, 256>>>(hidden, hf16, hbh, hbl);
    prep_weights<<<8192, 256>>>(w_attn, w_proj, wkh, wkl, wqv, wp);

    // 1) Q and V sections, fp16, packed output
    dim3 gqv(16, NROWS / 128);
    gemm_f16<<<gqv, 256>>>(hf16, wqv, b_attn, nullptr, qvh,
                           0, EMB, 8, 1024, 1);

    // 2) K section, bf16x3 BK=32 cp.async, FUSED KIVI quant -> packed fp16
    dim3 gk(EMB / 128, NROWS / 128);
    gemm_bf16k<<<gk, 256, G3_SMEM_BYTES>>>(hbh, hbl, wkh, wkl, b_attn + EMB,
                                           kh, EMB);

    // 3) attention (cp.async double-buffered KV)
    attn_f16<<<BATCH * NH * (S_LEN / 128), 256, att_smem>>>(qvh, kh, mask, oh);

    // 4) out projection, fp16, fp32 output
    dim3 gp(EMB / 128, NROWS / 128);
    gemm_f16<<<gp, 256>>>(oh, wp, b_proj, out, nullptr,
                          EMB, EMB, 16, 0, 0);
}

// round 15
// speedup vs baseline: 1.0203x; 1.0203x over previous
#include <cuda_runtime.h>
#include <cuda_bf16.h>
#include <cuda_fp16.h>
#include <math.h>
#include <stdint.h>

#define BATCH 4
#define S_LEN 1024
#define EMB   1024
#define NH    16
#define HD    64
#define NROWS (BATCH * S_LEN)

// ---------------- scratch (no allocations allowed) ----------------
__device__ uint32_t g_hf16[NROWS * 512];        // hidden fp16 pairs [m][kp]
__device__ uint32_t g_hbh [NROWS * 512];        // hidden bf16 hi    [m][kp]
__device__ uint32_t g_hbl [NROWS * 512];        // hidden bf16 lo    [m][kp]
__device__ uint32_t g_qvh [NROWS * 1024];       // Q|V fp16 pairs: [row][kp], Q kp<512, V kp>=512
__device__ uint32_t g_kh  [NROWS * 512];        // K quantized fp16 pairs [row][kp]
__device__ uint32_t g_oh  [NROWS * 512];        // attention out fp16 pairs [row][kp]
__device__ uint32_t g_wkh [EMB * 512];          // Wk bf16 hi, [n][kp]
__device__ uint32_t g_wkl [EMB * 512];          // Wk bf16 lo, [n][kp]
__device__ uint32_t g_wqv [2048 * 512];         // Wq|Wv fp16, [n][kp]
__device__ uint32_t g_wp  [EMB * 512];          // Wproj fp16, [n][kp]

// ---------------- helpers ----------------
__device__ __forceinline__ void mma16bf(float* d, const uint32_t* a, uint32_t b0, uint32_t b1) {
    asm volatile(
        "mma.sync.aligned.m16n8k16.row.col.f32.bf16.bf16.f32 "
        "{%0,%1,%2,%3}, {%4,%5,%6,%7}, {%8,%9}, {%0,%1,%2,%3};"
        : "+f"(d[0]), "+f"(d[1]), "+f"(d[2]), "+f"(d[3])
        : "r"(a[0]), "r"(a[1]), "r"(a[2]), "r"(a[3]), "r"(b0), "r"(b1));
}

__device__ __forceinline__ void mma16f(float* d, const uint32_t* a, uint32_t b0, uint32_t b1) {
    asm volatile(
        "mma.sync.aligned.m16n8k16.row.col.f32.f16.f16.f32 "
        "{%0,%1,%2,%3}, {%4,%5,%6,%7}, {%8,%9}, {%0,%1,%2,%3};"
        : "+f"(d[0]), "+f"(d[1]), "+f"(d[2]), "+f"(d[3])
        : "r"(a[0]), "r"(a[1]), "r"(a[2]), "r"(a[3]), "r"(b0), "r"(b1));
}

__device__ __forceinline__ void ldsm_x4(uint32_t* r, uint32_t addr) {
    asm volatile("ldmatrix.sync.aligned.m8n8.x4.shared.b16 {%0,%1,%2,%3}, [%4];"
        : "=r"(r[0]), "=r"(r[1]), "=r"(r[2]), "=r"(r[3]) : "r"(addr));
}

__device__ __forceinline__ void ldsm_x4_trans(uint32_t* r, uint32_t addr) {
    asm volatile("ldmatrix.sync.aligned.m8n8.x4.trans.shared.b16 {%0,%1,%2,%3}, [%4];"
        : "=r"(r[0]), "=r"(r[1]), "=r"(r[2]), "=r"(r[3]) : "r"(addr));
}

#define CP_ASYNC16(saddr, gptr) \
    asm volatile("cp.async.cg.shared.global [%0], [%1], 16;" \
        :: "r"(saddr), "l"(gptr) : "memory")
#define CP_COMMIT() asm volatile("cp.async.commit_group;" ::: "memory")
#define CP_WAIT0()  asm volatile("cp.async.wait_group 0;" ::: "memory")

__device__ __forceinline__ uint32_t pack_bf2(float x0, float x1) {
    __nv_bfloat162 p = __floats2bfloat162_rn(x0, x1);
    return *(uint32_t*)&p;
}

__device__ __forceinline__ uint32_t pack_h2(float x0, float x1) {
    __half2 p = __floats2half2_rn(x0, x1);
    return *(uint32_t*)&p;
}

__device__ __forceinline__ void split_bf(float x, float& h, float& l) {
    __nv_bfloat16 hb = __float2bfloat16_rn(x);
    h = __bfloat162float(hb);
    l = x - h;
}

__device__ __forceinline__ uint32_t kivi2(float v0, float v1, float ma) {
    float scale = ma * (1.0f / 1.5f);
    float safe = (scale == 0.0f) ? 1.0f : scale;
    float c0 = fminf(fmaxf(rintf(v0 / safe + 1.5f), 0.0f), 3.0f);
    float c1 = fminf(fmaxf(rintf(v1 / safe + 1.5f), 0.0f), 3.0f);
    return pack_h2((c0 - 1.5f) * scale, (c1 - 1.5f) * scale);
}

// ---------------- prep kernels ----------------
__global__ __launch_bounds__(256) void prep_hidden(
    const float* __restrict__ hid, uint32_t* __restrict__ hf,
    uint32_t* __restrict__ hh, uint32_t* __restrict__ hl)
{
    int idx = blockIdx.x * 256 + threadIdx.x;
    int kp = idx & 511;
    int m  = idx >> 9;
    float2 v = *(const float2*)(hid + (size_t)m * EMB + 2 * kp);
    hf[idx] = pack_h2(v.x, v.y);
    float h0, l0, h1, l1;
    split_bf(v.x, h0, l0);
    split_bf(v.y, h1, l1);
    hh[idx] = pack_bf2(h0, h1);
    hl[idx] = pack_bf2(l0, l1);
}

__global__ __launch_bounds__(256) void prep_weights(
    const float* __restrict__ wa, const float* __restrict__ wpj,
    uint32_t* __restrict__ wkh, uint32_t* __restrict__ wkl,
    uint32_t* __restrict__ wqv, uint32_t* __restrict__ wp)
{
    int bidx = blockIdx.x;
    if (bidx < 2048) {
        int idx = bidx * 256 + threadIdx.x;
        int n  = idx & 1023;
        int kp = idx >> 10;
        float x0 = wa[(size_t)(2 * kp)     * (3 * EMB) + EMB + n];
        float x1 = wa[(size_t)(2 * kp + 1) * (3 * EMB) + EMB + n];
        float h0, l0, h1, l1;
        split_bf(x0, h0, l0);
        split_bf(x1, h1, l1);
        wkh[(size_t)n * 512 + kp] = pack_bf2(h0, h1);
        wkl[(size_t)n * 512 + kp] = pack_bf2(l0, l1);
    } else if (bidx < 6144) {
        int idx = (bidx - 2048) * 256 + threadIdx.x;
        int n  = idx & 2047;
        int kp = idx >> 11;
        int col = n + ((n >= 1024) ? 1024 : 0);
        float x0 = wa[(size_t)(2 * kp)     * (3 * EMB) + col];
        float x1 = wa[(size_t)(2 * kp + 1) * (3 * EMB) + col];
        wqv[(size_t)n * 512 + kp] = pack_h2(x0, x1);
    } else {
        int idx = (bidx - 6144) * 256 + threadIdx.x;
        int n  = idx & 1023;
        int kp = idx >> 10;
        float x0 = wpj[(size_t)(2 * kp)     * EMB + n];
        float x1 = wpj[(size_t)(2 * kp + 1) * EMB + n];
        wp[(size_t)n * 512 + kp] = pack_h2(x0, x1);
    }
}

// ---------------- fp16 GEMM: cp.async double-buffered, BK=32 ----------------
#define GF_S 20
#define GF_BUF (128 * GF_S)

__global__ __launch_bounds__(256, 2) void gemm_f16(
    const uint32_t* __restrict__ Apk, const uint32_t* __restrict__ Bp,
    const float* __restrict__ bias, float* __restrict__ C,
    uint32_t* __restrict__ Cp, int ldc, int K, int nsplit, int gap, int pack_out)
{
    __shared__ uint32_t As[2][GF_BUF];
    __shared__ uint32_t Bs[2][GF_BUF];

    const int tid = threadIdx.x;
    const int bx = blockIdx.x, by = blockIdx.y;
    const int bcol = bx * 128 + ((bx >= nsplit) ? gap : 0);
    const int lane = tid & 31, wid = tid >> 5;
    const int g = lane >> 2, tg = lane & 3;
    const int wm = (wid >> 2) * 64, wn = (wid & 3) * 32;

    const int la_row = lane & 15, la_chunk = (lane >> 4) * 4;

    const uint32_t as_base = (uint32_t)__cvta_generic_to_shared(As);
    const uint32_t bs_base = (uint32_t)__cvta_generic_to_shared(Bs);

    const int arow = tid >> 1, akp = (tid & 1) * 8;
    const uint32_t* App = Apk + (size_t)(by * 128 + arow) * 512 + akp;
    const uint32_t* Bpp = Bp  + (size_t)(bx * 128 + arow) * 512 + akp;

    auto load_tile = [&](int t, int bb) {
        const uint32_t da = as_base + (bb * GF_BUF + arow * GF_S + akp) * 4;
        const uint32_t db = bs_base + (bb * GF_BUF + arow * GF_S + akp) * 4;
        CP_ASYNC16(da,      App + t * 16);
        CP_ASYNC16(da + 16, App + t * 16 + 4);
        CP_ASYNC16(db,      Bpp + t * 16);
        CP_ASYNC16(db + 16, Bpp + t * 16 + 4);
    };

    float acc[4][4][4];
    #pragma unroll
    for (int mt = 0; mt < 4; mt++)
        #pragma unroll
        for (int nt = 0; nt < 4; nt++)
            #pragma unroll
            for (int i = 0; i < 4; i++) acc[mt][nt][i] = 0.0f;

    load_tile(0, 0);
    CP_COMMIT();
    CP_WAIT0();
    __syncthreads();

    const int ntiles = K >> 5;
    int buf = 0;
    for (int t = 0; t < ntiles; ++t) {
        if (t + 1 < ntiles) {
            load_tile(t + 1, buf ^ 1);
            CP_COMMIT();
        }

        const uint32_t as0 = as_base + (buf * GF_BUF) * 4;
        const uint32_t bs0 = bs_base + (buf * GF_BUF) * 4;

        #pragma unroll
        for (int ks = 0; ks < 2; ++ks) {
            const int kb = ks * 8;
            uint32_t af[4][4], bq[2][4];
            #pragma unroll
            for (int mt = 0; mt < 4; mt++)
                ldsm_x4(af[mt], as0 + ((wm + mt * 16 + la_row) * GF_S + kb + la_chunk) * 4);
            #pragma unroll
            for (int np = 0; np < 2; np++)
                ldsm_x4(bq[np], bs0 + ((wn + np * 16 + la_row) * GF_S + kb + la_chunk) * 4);
            #pragma unroll
            for (int mt = 0; mt < 4; mt++)
                #pragma unroll
                for (int np = 0; np < 2; np++) {
                    mma16f(acc[mt][2 * np + 0], af[mt], bq[np][0], bq[np][2]);
                    mma16f(acc[mt][2 * np + 1], af[mt], bq[np][1], bq[np][3]);
                }
        }

        if (t + 1 < ntiles) CP_WAIT0();
        __syncthreads();
        buf ^= 1;
    }

    #pragma unroll
    for (int mt = 0; mt < 4; mt++) {
        #pragma unroll
        for (int nt = 0; nt < 4; nt++) {
            const int col = bcol + wn + nt * 8 + 2 * tg;
            const float bv0 = bias[col], bv1 = bias[col + 1];
            const int row0 = by * 128 + wm + mt * 16 + g;
            float o00 = acc[mt][nt][0] + bv0, o01 = acc[mt][nt][1] + bv1;
            float o10 = acc[mt][nt][2] + bv0, o11 = acc[mt][nt][3] + bv1;
            if (pack_out) {
                const int kp = (col >= 2048) ? (512 + ((col - 2048) >> 1)) : (col >> 1);
                Cp[(size_t)row0 * 1024 + kp]       = pack_h2(o00, o01);
                Cp[(size_t)(row0 + 8) * 1024 + kp] = pack_h2(o10, o11);
            } else {
                *(float2*)(C + (size_t)row0 * ldc + col)       = make_float2(o00, o01);
                *(float2*)(C + (size_t)(row0 + 8) * ldc + col) = make_float2(o10, o11);
            }
        }
    }
}

// ---------------- bf16x3 GEMM for K (R13 known-good): BK=16, reg prefetch ----------------
#define G3_S 12
#define G3_BUF (128 * G3_S)
#define G3_SMEM_BYTES (8 * G3_BUF * 4)

__global__ __launch_bounds__(256, 2) void gemm_bf16k(
    const uint32_t* __restrict__ Ahg, const uint32_t* __restrict__ Alg,
    const uint32_t* __restrict__ Bhg, const uint32_t* __restrict__ Blg,
    const float* __restrict__ bias, uint32_t* __restrict__ Kp, int K)
{
    extern __shared__ uint32_t s3[];
    uint32_t* Ah = s3;
    uint32_t* Al = Ah + 2 * G3_BUF;
    uint32_t* Bh = Al + 2 * G3_BUF;
    uint32_t* Bl = Bh + 2 * G3_BUF;

    const int tid = threadIdx.x;
    const int bx = blockIdx.x, by = blockIdx.y;
    const int lane = tid & 31, wid = tid >> 5;
    const int g = lane >> 2, tg = lane & 3;
    const int wm = (wid >> 2) * 64, wn = (wid & 3) * 32;

    const int la_row = lane & 15, la_chunk = (lane >> 4) * 4;

    const uint32_t ah_base = (uint32_t)__cvta_generic_to_shared(Ah);
    const uint32_t al_base = (uint32_t)__cvta_generic_to_shared(Al);
    const uint32_t bh_base = (uint32_t)__cvta_generic_to_shared(Bh);
    const uint32_t bl_base = (uint32_t)__cvta_generic_to_shared(Bl);

    const int arow = tid >> 1, akp = (tid & 1) * 4;
    const uint32_t* Ahp = Ahg + (size_t)(by * 128 + arow) * 512 + akp;
    const uint32_t* Alp = Alg + (size_t)(by * 128 + arow) * 512 + akp;
    const uint32_t* Bhp = Bhg + (size_t)(bx * 128 + arow) * 512 + akp;
    const uint32_t* Blp = Blg + (size_t)(bx * 128 + arow) * 512 + akp;

    float acc[4][4][4];
    #pragma unroll
    for (int mt = 0; mt < 4; mt++)
        #pragma unroll
        for (int nt = 0; nt < 4; nt++)
            #pragma unroll
            for (int i = 0; i < 4; i++) acc[mt][nt][i] = 0.0f;

    uint4 pah = *(const uint4*)(Ahp);
    uint4 pal = *(const uint4*)(Alp);
    uint4 pbh = *(const uint4*)(Bhp);
    uint4 pbl = *(const uint4*)(Blp);

    const int ntiles = K >> 4;
    int buf = 0;
    {
        *(uint4*)&Ah[arow * G3_S + akp] = pah;
        *(uint4*)&Al[arow * G3_S + akp] = pal;
        *(uint4*)&Bh[arow * G3_S + akp] = pbh;
        *(uint4*)&Bl[arow * G3_S + akp] = pbl;
    }
    __syncthreads();

    for (int t = 0; t < ntiles; ++t) {
        if (t + 1 < ntiles) {
            pah = *(const uint4*)(Ahp + (t + 1) * 8);
            pal = *(const uint4*)(Alp + (t + 1) * 8);
            pbh = *(const uint4*)(Bhp + (t + 1) * 8);
            pbl = *(const uint4*)(Blp + (t + 1) * 8);
        }

        const uint32_t ah0 = ah_base + (buf * G3_BUF) * 4;
        const uint32_t al0 = al_base + (buf * G3_BUF) * 4;
        const uint32_t bh0 = bh_base + (buf * G3_BUF) * 4;
        const uint32_t bl0 = bl_base + (buf * G3_BUF) * 4;

        uint32_t afh[4][4], afl[4][4], bqh[2][4], bql[2][4];
        #pragma unroll
        for (int mt = 0; mt < 4; mt++) {
            const uint32_t off = ((wm + mt * 16 + la_row) * G3_S + la_chunk) * 4;
            ldsm_x4(afh[mt], ah0 + off);
            ldsm_x4(afl[mt], al0 + off);
        }
        #pragma unroll
        for (int np = 0; np < 2; np++) {
            const uint32_t off = ((wn + np * 16 + la_row) * G3_S + la_chunk) * 4;
            ldsm_x4(bqh[np], bh0 + off);
            ldsm_x4(bql[np], bl0 + off);
        }
        #pragma unroll
        for (int mt = 0; mt < 4; mt++)
            #pragma unroll
            for (int np = 0; np < 2; np++) {
                float* a0 = acc[mt][2 * np + 0];
                float* a1 = acc[mt][2 * np + 1];
                mma16bf(a0, afh[mt], bqh[np][0], bqh[np][2]);
                mma16bf(a0, afh[mt], bql[np][0], bql[np][2]);
                mma16bf(a0, afl[mt], bqh[np][0], bqh[np][2]);
                mma16bf(a1, afh[mt], bqh[np][1], bqh[np][3]);
                mma16bf(a1, afh[mt], bql[np][1], bql[np][3]);
                mma16bf(a1, afl[mt], bqh[np][1], bqh[np][3]);
            }

        if (t + 1 < ntiles) {
            const int nb = buf ^ 1;
            __syncthreads();
            *(uint4*)&Ah[nb * G3_BUF + arow * G3_S + akp] = pah;
            *(uint4*)&Al[nb * G3_BUF + arow * G3_S + akp] = pal;
            *(uint4*)&Bh[nb * G3_BUF + arow * G3_S + akp] = pbh;
            *(uint4*)&Bl[nb * G3_BUF + arow * G3_S + akp] = pbl;
            __syncthreads();
            buf = nb;
        }
    }

    // ---- epilogue: bias + KIVI 2-bit quant (group = tg-pair) + pack fp16 ----
    #pragma unroll
    for (int mt = 0; mt < 4; mt++) {
        #pragma unroll
        for (int nt = 0; nt < 4; nt++) {
            const int col = bx * 128 + wn + nt * 8 + 2 * tg;
            const float bv0 = bias[col], bv1 = bias[col + 1];
            const int row0 = by * 128 + wm + mt * 16 + g;
            float v00 = acc[mt][nt][0] + bv0, v01 = acc[mt][nt][1] + bv1;
            float v10 = acc[mt][nt][2] + bv0, v11 = acc[mt][nt][3] + bv1;
            float ma0 = fmaxf(fabsf(v00), fabsf(v01));
            float ma1 = fmaxf(fabsf(v10), fabsf(v11));
            ma0 = fmaxf(ma0, __shfl_xor_sync(0xffffffffu, ma0, 1));
            ma1 = fmaxf(ma1, __shfl_xor_sync(0xffffffffu, ma1, 1));
            const int kp = col >> 1;
            Kp[(size_t)row0 * 512 + kp]       = kivi2(v00, v01, ma0);
            Kp[(size_t)(row0 + 8) * 512 + kp] = kivi2(v10, v11, ma1);
        }
    }
}

// ---------------- Flash attention: cp.async double-buffered KV pipeline ----------------
#define SQH 36
#define ATT_FLOATS (128 * SQH + 2 * 64 * SQH + 128 * SQH + 2 * 64 * SQH + 2 * 64)

__global__ __launch_bounds__(256, 2) void attn_f16(
    const uint32_t* __restrict__ qvh, const uint32_t* __restrict__ kh,
    const float* __restrict__ mask, uint32_t* __restrict__ outp)
{
    extern __shared__ uint32_t smu[];
    uint32_t* Qs = smu;                       // [128][36]
    uint32_t* Ks = Qs + 128 * SQH;            // [2][64][36]
    uint32_t* Ps = Ks + 2 * 64 * SQH;         // [128][36]
    uint32_t* Vs = Ps + 128 * SQH;            // [2][64][36]
    float*    Ms = (float*)(Vs + 2 * 64 * SQH);  // [2][64]

    const int tid = threadIdx.x, lane = tid & 31, wid = tid >> 5;
    const int g = lane >> 2, tg = lane & 3;
    const int m0 = wid * 16;

    const int la_row = lane & 15, la_chunk = (lane >> 4) * 4;

    const uint32_t qs_base = (uint32_t)__cvta_generic_to_shared(Qs);
    const uint32_t ks_base = (uint32_t)__cvta_generic_to_shared(Ks);
    const uint32_t ps_base = (uint32_t)__cvta_generic_to_shared(Ps);
    const uint32_t vs_base = (uint32_t)__cvta_generic_to_shared(Vs);
    const uint32_t ms_base = (uint32_t)__cvta_generic_to_shared(Ms);

    const int bid = blockIdx.x;
    const int qt = bid & 7;
    const int h  = (bid >> 3) & 15;
    const int b  = bid >> 7;

    const uint32_t* qp = qvh + ((size_t)(b * S_LEN) + qt * 128) * 1024 + h * 32;
    const uint32_t* vp = qvh + ((size_t)(b * S_LEN)) * 1024 + 512 + h * 32;
    const uint32_t* kp = kh  + ((size_t)(b * S_LEN)) * 512 + h * 32;
    const float*    mp = mask + b * S_LEN;

    auto load_tile = [&](int ktn, int bb) {
        #pragma unroll
        for (int i = 0; i < 2; i++) {
            int f = tid + 256 * i;
            int row = f >> 3, w4 = (f & 7) * 4;
            int key = (ktn << 6) + row;
            CP_ASYNC16(ks_base + ((bb * 64 + row) * SQH + w4) * 4,
                       kp + (size_t)key * 512 + w4);
            CP_ASYNC16(vs_base + ((bb * 64 + row) * SQH + w4) * 4,
                       vp + (size_t)key * 1024 + w4);
        }
        if (tid < 16)
            CP_ASYNC16(ms_base + (bb * 64 + tid * 4) * 4, mp + (ktn << 6) + tid * 4);
    };

    load_tile(0, 0);
    CP_COMMIT();
    #pragma unroll
    for (int i = 0; i < 4; i++) {
        int f = tid + 256 * i;
        int row = f >> 3, w4 = (f & 7) * 4;
        uint4 u = *(const uint4*)(qp + (size_t)row * 1024 + w4);
        *(uint4*)&Qs[row * SQH + w4] = u;
    }

    float m_i[2] = {-INFINITY, -INFINITY}, l_i[2] = {0.0f, 0.0f};
    float oa[8][4];
    #pragma unroll
    for (int nt = 0; nt < 8; nt++)
        #pragma unroll
        for (int i = 0; i < 4; i++) oa[nt][i] = 0.0f;

    CP_WAIT0();
    __syncthreads();

    int buf = 0;
    const int NT = S_LEN / 64;
    for (int kt = 0; kt < NT; ++kt) {
        if (kt + 1 < NT) {
            load_tile(kt + 1, buf ^ 1);
            CP_COMMIT();
        }

        const uint32_t ksb = ks_base + (buf * 64 * SQH) * 4;
        const uint32_t vsb = vs_base + (buf * 64 * SQH) * 4;
        const float*   msb = Ms + buf * 64;

        // ---- S = Q K^T ----
        float sacc[8][4];
        #pragma unroll
        for (int nt = 0; nt < 8; nt++)
            #pragma unroll
            for (int i = 0; i < 4; i++) sacc[nt][i] = 0.0f;

        #pragma unroll
        for (int ks = 0; ks < 4; ++ks) {
            const int kb = ks * 8;
            uint32_t af[4];
            ldsm_x4(af, qs_base + ((m0 + la_row) * SQH + kb + la_chunk) * 4);
            #pragma unroll
            for (int np = 0; np < 4; ++np) {
                uint32_t bq[4];
                ldsm_x4(bq, ksb + ((np * 16 + la_row) * SQH + kb + la_chunk) * 4);
                mma16f(sacc[2 * np + 0], af, bq[0], bq[2]);
                mma16f(sacc[2 * np + 1], af, bq[1], bq[3]);
            }
        }

        // ---- online softmax ----
        #pragma unroll
        for (int rr = 0; rr < 2; ++rr) {
            float mx = -INFINITY;
            #pragma unroll
            for (int nt = 0; nt < 8; nt++) {
                const int c0 = nt * 8 + 2 * tg;
                float s0 = (sacc[nt][rr * 2 + 0] + msb[c0]) * 0.125f;
                float s1 = (sacc[nt][rr * 2 + 1] + msb[c0 + 1]) * 0.125f;
                sacc[nt][rr * 2 + 0] = s0;
                sacc[nt][rr * 2 + 1] = s1;
                mx = fmaxf(mx, fmaxf(s0, s1));
            }
            mx = fmaxf(mx, __shfl_xor_sync(0xffffffffu, mx, 1));
            mx = fmaxf(mx, __shfl_xor_sync(0xffffffffu, mx, 2));
            const float mnew = fmaxf(m_i[rr], mx);
            const float alpha = __expf(m_i[rr] - mnew);
            float rs = 0.0f;
            const int row = m0 + g + rr * 8;
            #pragma unroll
            for (int nt = 0; nt < 8; nt++) {
                float p0 = __expf(sacc[nt][rr * 2 + 0] - mnew);
                float p1 = __expf(sacc[nt][rr * 2 + 1] - mnew);
                rs += p0 + p1;
                Ps[row * SQH + nt * 4 + tg] = pack_h2(p0, p1);
            }
            rs += __shfl_xor_sync(0xffffffffu, rs, 1);
            rs += __shfl_xor_sync(0xffffffffu, rs, 2);
            l_i[rr] = l_i[rr] * alpha + rs;
            m_i[rr] = mnew;
            #pragma unroll
            for (int nt = 0; nt < 8; nt++) {
                oa[nt][rr * 2 + 0] *= alpha;
                oa[nt][rr * 2 + 1] *= alpha;
            }
        }
        __syncwarp();   // P rows are warp-private

        // ---- O += P V ----
        #pragma unroll
        for (int ks = 0; ks < 4; ++ks) {
            const int kb = ks * 8;
            uint32_t ap[4];
            ldsm_x4(ap, ps_base + ((m0 + la_row) * SQH + kb + la_chunk) * 4);
            #pragma unroll
            for (int np = 0; np < 4; ++np) {
                uint32_t bv[4];
                ldsm_x4_trans(bv, vsb +
                    ((ks * 16 + la_row) * SQH + (2 * np + (lane >> 4)) * 4) * 4);
                mma16f(oa[2 * np + 0], ap, bv[0], bv[1]);
                mma16f(oa[2 * np + 1], ap, bv[2], bv[3]);
            }
        }

        if (kt + 1 < NT) CP_WAIT0();
        __syncthreads();
        buf ^= 1;
    }

    // ---- epilogue: packed fp16 output [row][kp] for the proj GEMM ----
    #pragma unroll
    for (int rr = 0; rr < 2; ++rr) {
        const float inv = 1.0f / l_i[rr];
        const int srow = qt * 128 + m0 + g + rr * 8;
        uint32_t* op = outp + ((size_t)(b * S_LEN + srow)) * 512 + h * 32;
        #pragma unroll
        for (int nt = 0; nt < 8; nt++)
            op[nt * 4 + tg] = pack_h2(oa[nt][rr * 2 + 0] * inv, oa[nt][rr * 2 + 1] * inv);
    }
}

// ---------------- launch ----------------
extern "C" void kernel_launch(void* const* d_in, const int* in_sizes, int n_in,
                              void* d_out, int out_size)
{
    const float* hidden = (const float*)d_in[0];
    const float* mask   = (const float*)d_in[1];
    const float* w_attn = (const float*)d_in[2];
    const float* b_attn = (const float*)d_in[3];
    const float* w_proj = (const float*)d_in[4];
    const float* b_proj = (const float*)d_in[5];
    float* out = (float*)d_out;

    uint32_t *hf16, *hbh, *hbl, *qvh, *kh, *oh, *wkh, *wkl, *wqv, *wp;
    cudaGetSymbolAddress((void**)&hf16, g_hf16);
    cudaGetSymbolAddress((void**)&hbh,  g_hbh);
    cudaGetSymbolAddress((void**)&hbl,  g_hbl);
    cudaGetSymbolAddress((void**)&qvh,  g_qvh);
    cudaGetSymbolAddress((void**)&kh,   g_kh);
    cudaGetSymbolAddress((void**)&oh,   g_oh);
    cudaGetSymbolAddress((void**)&wkh,  g_wkh);
    cudaGetSymbolAddress((void**)&wkl,  g_wkl);
    cudaGetSymbolAddress((void**)&wqv,  g_wqv);
    cudaGetSymbolAddress((void**)&wp,   g_wp);

    const int att_smem = ATT_FLOATS * (int)sizeof(float);
    cudaFuncSetAttribute(attn_f16,
                         cudaFuncAttributeMaxDynamicSharedMemorySize, att_smem);
    cudaFuncSetAttribute(gemm_bf16k,
                         cudaFuncAttributeMaxDynamicSharedMemorySize, G3_SMEM_BYTES);

    // 0) prep: activations + fused weight packing
    prep_hidden<<<NROWS * 512 / 256, 256>>>(hidden, hf16, hbh, hbl);
    prep_weights<<<8192, 256>>>(w_attn, w_proj, wkh, wkl, wqv, wp);

    // 1) Q and V sections, fp16, packed output
    dim3 gqv(16, NROWS / 128);
    gemm_f16<<<gqv, 256>>>(hf16, wqv, b_attn, nullptr, qvh,
                           0, EMB, 8, 1024, 1);

    // 2) K section, bf16x3 (R13 config), FUSED KIVI quant -> packed fp16
    dim3 gk(EMB / 128, NROWS / 128);
    gemm_bf16k<<<gk, 256, G3_SMEM_BYTES>>>(hbh, hbl, wkh, wkl, b_attn + EMB,
                                           kh, EMB);

    // 3) attention (cp.async double-buffered KV)
    attn_f16<<<BATCH * NH * (S_LEN / 128), 256, att_smem>>>(qvh, kh, mask, oh);

    // 4) out projection, fp16, fp32 output
    dim3 gp(EMB / 128, NROWS / 128);
    gemm_f16<<<gp, 256>>>(oh, wp, b_proj, out, nullptr,
                          EMB, EMB, 16, 0, 0);
}

// round 16
// speedup vs baseline: 1.0627x; 1.0415x over previous
#include <cuda_runtime.h>
#include <cuda_bf16.h>
#include <cuda_fp16.h>
#include <math.h>
#include <stdint.h>

#define BATCH 4
#define S_LEN 1024
#define EMB   1024
#define NH    16
#define HD    64
#define NROWS (BATCH * S_LEN)

// ---------------- scratch (no allocations allowed) ----------------
__device__ uint32_t g_hf16[NROWS * 512];        // hidden fp16 pairs [m][kp]
__device__ uint32_t g_hbh [NROWS * 512];        // hidden bf16 hi    [m][kp]
__device__ uint32_t g_hbl [NROWS * 512];        // hidden bf16 lo    [m][kp]
__device__ uint32_t g_qvh [NROWS * 1024];       // Q|V fp16 pairs: [row][kp], Q kp<512, V kp>=512
__device__ uint32_t g_kh  [NROWS * 512];        // K quantized fp16 pairs [row][kp]
__device__ uint32_t g_oh  [NROWS * 512];        // attention out fp16 pairs [row][kp]
__device__ uint32_t g_wkh [EMB * 512];          // Wk bf16 hi, [n][kp]
__device__ uint32_t g_wkl [EMB * 512];          // Wk bf16 lo, [n][kp]
__device__ uint32_t g_wqv [2048 * 512];         // Wq|Wv fp16, [n][kp]
__device__ uint32_t g_wp  [EMB * 512];          // Wproj fp16, [n][kp]

// ---------------- helpers ----------------
__device__ __forceinline__ void mma16bf(float* d, const uint32_t* a, uint32_t b0, uint32_t b1) {
    asm volatile(
        "mma.sync.aligned.m16n8k16.row.col.f32.bf16.bf16.f32 "
        "{%0,%1,%2,%3}, {%4,%5,%6,%7}, {%8,%9}, {%0,%1,%2,%3};"
        : "+f"(d[0]), "+f"(d[1]), "+f"(d[2]), "+f"(d[3])
        : "r"(a[0]), "r"(a[1]), "r"(a[2]), "r"(a[3]), "r"(b0), "r"(b1));
}

__device__ __forceinline__ void mma16f(float* d, const uint32_t* a, uint32_t b0, uint32_t b1) {
    asm volatile(
        "mma.sync.aligned.m16n8k16.row.col.f32.f16.f16.f32 "
        "{%0,%1,%2,%3}, {%4,%5,%6,%7}, {%8,%9}, {%0,%1,%2,%3};"
        : "+f"(d[0]), "+f"(d[1]), "+f"(d[2]), "+f"(d[3])
        : "r"(a[0]), "r"(a[1]), "r"(a[2]), "r"(a[3]), "r"(b0), "r"(b1));
}

__device__ __forceinline__ void ldsm_x4(uint32_t* r, uint32_t addr) {
    asm volatile("ldmatrix.sync.aligned.m8n8.x4.shared.b16 {%0,%1,%2,%3}, [%4];"
        : "=r"(r[0]), "=r"(r[1]), "=r"(r[2]), "=r"(r[3]) : "r"(addr));
}

__device__ __forceinline__ void ldsm_x4_trans(uint32_t* r, uint32_t addr) {
    asm volatile("ldmatrix.sync.aligned.m8n8.x4.trans.shared.b16 {%0,%1,%2,%3}, [%4];"
        : "=r"(r[0]), "=r"(r[1]), "=r"(r[2]), "=r"(r[3]) : "r"(addr));
}

#define CP_ASYNC16(saddr, gptr) \
    asm volatile("cp.async.cg.shared.global [%0], [%1], 16;" \
        :: "r"(saddr), "l"(gptr) : "memory")
#define CP_COMMIT() asm volatile("cp.async.commit_group;" ::: "memory")
#define CP_WAIT0()  asm volatile("cp.async.wait_group 0;" ::: "memory")

__device__ __forceinline__ uint32_t pack_bf2(float x0, float x1) {
    __nv_bfloat162 p = __floats2bfloat162_rn(x0, x1);
    return *(uint32_t*)&p;
}

__device__ __forceinline__ uint32_t pack_h2(float x0, float x1) {
    __half2 p = __floats2half2_rn(x0, x1);
    return *(uint32_t*)&p;
}

__device__ __forceinline__ void split_bf(float x, float& h, float& l) {
    __nv_bfloat16 hb = __float2bfloat16_rn(x);
    h = __bfloat162float(hb);
    l = x - h;
}

__device__ __forceinline__ uint32_t kivi2(float v0, float v1, float ma) {
    float scale = ma * (1.0f / 1.5f);
    float safe = (scale == 0.0f) ? 1.0f : scale;
    float c0 = fminf(fmaxf(rintf(v0 / safe + 1.5f), 0.0f), 3.0f);
    float c1 = fminf(fmaxf(rintf(v1 / safe + 1.5f), 0.0f), 3.0f);
    return pack_h2((c0 - 1.5f) * scale, (c1 - 1.5f) * scale);
}

// ---------------- fused prep: hidden packs + all weight packs ----------------
// blocks [0,8192): hidden; [8192,10240): Wk bf16 hi/lo; [10240,14336): Wqv; [14336,16384): Wp
__global__ __launch_bounds__(256) void prep_all(
    const float* __restrict__ hid, const float* __restrict__ wa,
    const float* __restrict__ wpj,
    uint32_t* __restrict__ hf, uint32_t* __restrict__ hh, uint32_t* __restrict__ hl,
    uint32_t* __restrict__ wkh, uint32_t* __restrict__ wkl,
    uint32_t* __restrict__ wqv, uint32_t* __restrict__ wp)
{
    int bidx = blockIdx.x;
    if (bidx < 8192) {
        int idx = bidx * 256 + threadIdx.x;
        int kp = idx & 511;
        int m  = idx >> 9;
        float2 v = *(const float2*)(hid + (size_t)m * EMB + 2 * kp);
        hf[idx] = pack_h2(v.x, v.y);
        float h0, l0, h1, l1;
        split_bf(v.x, h0, l0);
        split_bf(v.y, h1, l1);
        hh[idx] = pack_bf2(h0, h1);
        hl[idx] = pack_bf2(l0, l1);
    } else if (bidx < 10240) {
        int idx = (bidx - 8192) * 256 + threadIdx.x;
        int n  = idx & 1023;
        int kp = idx >> 10;
        float x0 = wa[(size_t)(2 * kp)     * (3 * EMB) + EMB + n];
        float x1 = wa[(size_t)(2 * kp + 1) * (3 * EMB) + EMB + n];
        float h0, l0, h1, l1;
        split_bf(x0, h0, l0);
        split_bf(x1, h1, l1);
        wkh[(size_t)n * 512 + kp] = pack_bf2(h0, h1);
        wkl[(size_t)n * 512 + kp] = pack_bf2(l0, l1);
    } else if (bidx < 14336) {
        int idx = (bidx - 10240) * 256 + threadIdx.x;
        int n  = idx & 2047;
        int kp = idx >> 11;
        int col = n + ((n >= 1024) ? 1024 : 0);
        float x0 = wa[(size_t)(2 * kp)     * (3 * EMB) + col];
        float x1 = wa[(size_t)(2 * kp + 1) * (3 * EMB) + col];
        wqv[(size_t)n * 512 + kp] = pack_h2(x0, x1);
    } else {
        int idx = (bidx - 14336) * 256 + threadIdx.x;
        int n  = idx & 1023;
        int kp = idx >> 10;
        float x0 = wpj[(size_t)(2 * kp)     * EMB + n];
        float x1 = wpj[(size_t)(2 * kp + 1) * EMB + n];
        wp[(size_t)n * 512 + kp] = pack_h2(x0, x1);
    }
}

// ---------------- tile constants ----------------
#define GF_S 20
#define GF_BUF (128 * GF_S)
#define G3_S 12
#define G3_BUF (128 * G3_S)
#define QK_SMEM_BYTES (8 * G3_BUF * 4)   // 48KB (>= fp16 path's 40KB)

// ---------------- fp16 GEMM body (cp.async, BK=32) ----------------
__device__ __forceinline__ void gemm_f16_body(
    uint32_t* sm, int bx, int by,
    const uint32_t* __restrict__ Apk, const uint32_t* __restrict__ Bp,
    const float* __restrict__ bias, float* __restrict__ C,
    uint32_t* __restrict__ Cp, int ldc, int K, int nsplit, int gap, int pack_out)
{
    uint32_t* As = sm;                  // [2][GF_BUF]
    uint32_t* Bs = As + 2 * GF_BUF;

    const int tid = threadIdx.x;
    const int bcol = bx * 128 + ((bx >= nsplit) ? gap : 0);
    const int lane = tid & 31, wid = tid >> 5;
    const int g = lane >> 2, tg = lane & 3;
    const int wm = (wid >> 2) * 64, wn = (wid & 3) * 32;

    const int la_row = lane & 15, la_chunk = (lane >> 4) * 4;

    const uint32_t as_base = (uint32_t)__cvta_generic_to_shared(As);
    const uint32_t bs_base = (uint32_t)__cvta_generic_to_shared(Bs);

    const int arow = tid >> 1, akp = (tid & 1) * 8;
    const uint32_t* App = Apk + (size_t)(by * 128 + arow) * 512 + akp;
    const uint32_t* Bpp = Bp  + (size_t)(bx * 128 + arow) * 512 + akp;

    auto load_tile = [&](int t, int bb) {
        const uint32_t da = as_base + (bb * GF_BUF + arow * GF_S + akp) * 4;
        const uint32_t db = bs_base + (bb * GF_BUF + arow * GF_S + akp) * 4;
        CP_ASYNC16(da,      App + t * 16);
        CP_ASYNC16(da + 16, App + t * 16 + 4);
        CP_ASYNC16(db,      Bpp + t * 16);
        CP_ASYNC16(db + 16, Bpp + t * 16 + 4);
    };

    float acc[4][4][4];
    #pragma unroll
    for (int mt = 0; mt < 4; mt++)
        #pragma unroll
        for (int nt = 0; nt < 4; nt++)
            #pragma unroll
            for (int i = 0; i < 4; i++) acc[mt][nt][i] = 0.0f;

    load_tile(0, 0);
    CP_COMMIT();
    CP_WAIT0();
    __syncthreads();

    const int ntiles = K >> 5;
    int buf = 0;
    for (int t = 0; t < ntiles; ++t) {
        if (t + 1 < ntiles) {
            load_tile(t + 1, buf ^ 1);
            CP_COMMIT();
        }

        const uint32_t as0 = as_base + (buf * GF_BUF) * 4;
        const uint32_t bs0 = bs_base + (buf * GF_BUF) * 4;

        #pragma unroll
        for (int ks = 0; ks < 2; ++ks) {
            const int kb = ks * 8;
            uint32_t af[4][4], bq[2][4];
            #pragma unroll
            for (int mt = 0; mt < 4; mt++)
                ldsm_x4(af[mt], as0 + ((wm + mt * 16 + la_row) * GF_S + kb + la_chunk) * 4);
            #pragma unroll
            for (int np = 0; np < 2; np++)
                ldsm_x4(bq[np], bs0 + ((wn + np * 16 + la_row) * GF_S + kb + la_chunk) * 4);
            #pragma unroll
            for (int mt = 0; mt < 4; mt++)
                #pragma unroll
                for (int np = 0; np < 2; np++) {
                    mma16f(acc[mt][2 * np + 0], af[mt], bq[np][0], bq[np][2]);
                    mma16f(acc[mt][2 * np + 1], af[mt], bq[np][1], bq[np][3]);
                }
        }

        if (t + 1 < ntiles) CP_WAIT0();
        __syncthreads();
        buf ^= 1;
    }

    #pragma unroll
    for (int mt = 0; mt < 4; mt++) {
        #pragma unroll
        for (int nt = 0; nt < 4; nt++) {
            const int col = bcol + wn + nt * 8 + 2 * tg;
            const float bv0 = bias[col], bv1 = bias[col + 1];
            const int row0 = by * 128 + wm + mt * 16 + g;
            float o00 = acc[mt][nt][0] + bv0, o01 = acc[mt][nt][1] + bv1;
            float o10 = acc[mt][nt][2] + bv0, o11 = acc[mt][nt][3] + bv1;
            if (pack_out) {
                const int kp = (col >= 2048) ? (512 + ((col - 2048) >> 1)) : (col >> 1);
                Cp[(size_t)row0 * 1024 + kp]       = pack_h2(o00, o01);
                Cp[(size_t)(row0 + 8) * 1024 + kp] = pack_h2(o10, o11);
            } else {
                *(float2*)(C + (size_t)row0 * ldc + col)       = make_float2(o00, o01);
                *(float2*)(C + (size_t)(row0 + 8) * ldc + col) = make_float2(o10, o11);
            }
        }
    }
}

// ---------------- bf16x3 K-GEMM body (BK=16, reg prefetch, fused quant) ----------------
__device__ __forceinline__ void gemm_bf16k_body(
    uint32_t* sm, int bx, int by,
    const uint32_t* __restrict__ Ahg, const uint32_t* __restrict__ Alg,
    const uint32_t* __restrict__ Bhg, const uint32_t* __restrict__ Blg,
    const float* __restrict__ bias, uint32_t* __restrict__ Kp, int K)
{
    uint32_t* Ah = sm;
    uint32_t* Al = Ah + 2 * G3_BUF;
    uint32_t* Bh = Al + 2 * G3_BUF;
    uint32_t* Bl = Bh + 2 * G3_BUF;

    const int tid = threadIdx.x;
    const int lane = tid & 31, wid = tid >> 5;
    const int g = lane >> 2, tg = lane & 3;
    const int wm = (wid >> 2) * 64, wn = (wid & 3) * 32;

    const int la_row = lane & 15, la_chunk = (lane >> 4) * 4;

    const uint32_t ah_base = (uint32_t)__cvta_generic_to_shared(Ah);
    const uint32_t al_base = (uint32_t)__cvta_generic_to_shared(Al);
    const uint32_t bh_base = (uint32_t)__cvta_generic_to_shared(Bh);
    const uint32_t bl_base = (uint32_t)__cvta_generic_to_shared(Bl);

    const int arow = tid >> 1, akp = (tid & 1) * 4;
    const uint32_t* Ahp = Ahg + (size_t)(by * 128 + arow) * 512 + akp;
    const uint32_t* Alp = Alg + (size_t)(by * 128 + arow) * 512 + akp;
    const uint32_t* Bhp = Bhg + (size_t)(bx * 128 + arow) * 512 + akp;
    const uint32_t* Blp = Blg + (size_t)(bx * 128 + arow) * 512 + akp;

    float acc[4][4][4];
    #pragma unroll
    for (int mt = 0; mt < 4; mt++)
        #pragma unroll
        for (int nt = 0; nt < 4; nt++)
            #pragma unroll
            for (int i = 0; i < 4; i++) acc[mt][nt][i] = 0.0f;

    uint4 pah = *(const uint4*)(Ahp);
    uint4 pal = *(const uint4*)(Alp);
    uint4 pbh = *(const uint4*)(Bhp);
    uint4 pbl = *(const uint4*)(Blp);

    const int ntiles = K >> 4;
    int buf = 0;
    {
        *(uint4*)&Ah[arow * G3_S + akp] = pah;
        *(uint4*)&Al[arow * G3_S + akp] = pal;
        *(uint4*)&Bh[arow * G3_S + akp] = pbh;
        *(uint4*)&Bl[arow * G3_S + akp] = pbl;
    }
    __syncthreads();

    for (int t = 0; t < ntiles; ++t) {
        if (t + 1 < ntiles) {
            pah = *(const uint4*)(Ahp + (t + 1) * 8);
            pal = *(const uint4*)(Alp + (t + 1) * 8);
            pbh = *(const uint4*)(Bhp + (t + 1) * 8);
            pbl = *(const uint4*)(Blp + (t + 1) * 8);
        }

        const uint32_t ah0 = ah_base + (buf * G3_BUF) * 4;
        const uint32_t al0 = al_base + (buf * G3_BUF) * 4;
        const uint32_t bh0 = bh_base + (buf * G3_BUF) * 4;
        const uint32_t bl0 = bl_base + (buf * G3_BUF) * 4;

        uint32_t afh[4][4], afl[4][4], bqh[2][4], bql[2][4];
        #pragma unroll
        for (int mt = 0; mt < 4; mt++) {
            const uint32_t off = ((wm + mt * 16 + la_row) * G3_S + la_chunk) * 4;
            ldsm_x4(afh[mt], ah0 + off);
            ldsm_x4(afl[mt], al0 + off);
        }
        #pragma unroll
        for (int np = 0; np < 2; np++) {
            const uint32_t off = ((wn + np * 16 + la_row) * G3_S + la_chunk) * 4;
            ldsm_x4(bqh[np], bh0 + off);
            ldsm_x4(bql[np], bl0 + off);
        }
        #pragma unroll
        for (int mt = 0; mt < 4; mt++)
            #pragma unroll
            for (int np = 0; np < 2; np++) {
                float* a0 = acc[mt][2 * np + 0];
                float* a1 = acc[mt][2 * np + 1];
                mma16bf(a0, afh[mt], bqh[np][0], bqh[np][2]);
                mma16bf(a0, afh[mt], bql[np][0], bql[np][2]);
                mma16bf(a0, afl[mt], bqh[np][0], bqh[np][2]);
                mma16bf(a1, afh[mt], bqh[np][1], bqh[np][3]);
                mma16bf(a1, afh[mt], bql[np][1], bql[np][3]);
                mma16bf(a1, afl[mt], bqh[np][1], bqh[np][3]);
            }

        if (t + 1 < ntiles) {
            const int nb = buf ^ 1;
            __syncthreads();
            *(uint4*)&Ah[nb * G3_BUF + arow * G3_S + akp] = pah;
            *(uint4*)&Al[nb * G3_BUF + arow * G3_S + akp] = pal;
            *(uint4*)&Bh[nb * G3_BUF + arow * G3_S + akp] = pbh;
            *(uint4*)&Bl[nb * G3_BUF + arow * G3_S + akp] = pbl;
            __syncthreads();
            buf = nb;
        }
    }

    // epilogue: bias + KIVI 2-bit quant (group = tg-pair) + pack fp16
    #pragma unroll
    for (int mt = 0; mt < 4; mt++) {
        #pragma unroll
        for (int nt = 0; nt < 4; nt++) {
            const int col = bx * 128 + wn + nt * 8 + 2 * tg;
            const float bv0 = bias[col], bv1 = bias[col + 1];
            const int row0 = by * 128 + wm + mt * 16 + g;
            float v00 = acc[mt][nt][0] + bv0, v01 = acc[mt][nt][1] + bv1;
            float v10 = acc[mt][nt][2] + bv0, v11 = acc[mt][nt][3] + bv1;
            float ma0 = fmaxf(fabsf(v00), fabsf(v01));
            float ma1 = fmaxf(fabsf(v10), fabsf(v11));
            ma0 = fmaxf(ma0, __shfl_xor_sync(0xffffffffu, ma0, 1));
            ma1 = fmaxf(ma1, __shfl_xor_sync(0xffffffffu, ma1, 1));
            const int kp = col >> 1;
            Kp[(size_t)row0 * 512 + kp]       = kivi2(v00, v01, ma0);
            Kp[(size_t)(row0 + 8) * 512 + kp] = kivi2(v10, v11, ma1);
        }
    }
}

// ---------------- fused QV + K GEMM launch: 768 blocks ----------------
// blocks [0,512): QV fp16 path (bx=bid&15, by=bid>>4)
// blocks [512,768): K bf16x3 path (bx=r&7, by=r>>3)
__global__ __launch_bounds__(256, 2) void gemm_qvk(
    const uint32_t* __restrict__ hf16,
    const uint32_t* __restrict__ hbh, const uint32_t* __restrict__ hbl,
    const uint32_t* __restrict__ wqv,
    const uint32_t* __restrict__ wkh, const uint32_t* __restrict__ wkl,
    const float* __restrict__ b_attn,
    uint32_t* __restrict__ qvh, uint32_t* __restrict__ kh)
{
    extern __shared__ uint32_t sm[];
    const int bid = blockIdx.x;
    if (bid < 512) {
        gemm_f16_body(sm, bid & 15, bid >> 4, hf16, wqv, b_attn,
                      nullptr, qvh, 0, EMB, 8, 1024, 1);
    } else {
        const int r = bid - 512;
        gemm_bf16k_body(sm, r & 7, r >> 3, hbh, hbl, wkh, wkl,
                        b_attn + EMB, kh, EMB);
    }
}

// ---------------- proj GEMM (standalone, fp32 out) ----------------
__global__ __launch_bounds__(256, 2) void gemm_proj(
    const uint32_t* __restrict__ oh, const uint32_t* __restrict__ wp,
    const float* __restrict__ b_proj, float* __restrict__ out)
{
    extern __shared__ uint32_t sm[];
    gemm_f16_body(sm, blockIdx.x, blockIdx.y, oh, wp, b_proj,
                  out, nullptr, EMB, EMB, 16, 0, 0);
}

// ---------------- Flash attention: cp.async double-buffered KV pipeline ----------------
#define SQH 36
#define ATT_FLOATS (128 * SQH + 2 * 64 * SQH + 128 * SQH + 2 * 64 * SQH + 2 * 64)

__global__ __launch_bounds__(256, 2) void attn_f16(
    const uint32_t* __restrict__ qvh, const uint32_t* __restrict__ kh,
    const float* __restrict__ mask, uint32_t* __restrict__ outp)
{
    extern __shared__ uint32_t smu[];
    uint32_t* Qs = smu;                       // [128][36]
    uint32_t* Ks = Qs + 128 * SQH;            // [2][64][36]
    uint32_t* Ps = Ks + 2 * 64 * SQH;         // [128][36]
    uint32_t* Vs = Ps + 128 * SQH;            // [2][64][36]
    float*    Ms = (float*)(Vs + 2 * 64 * SQH);  // [2][64]

    const int tid = threadIdx.x, lane = tid & 31, wid = tid >> 5;
    const int g = lane >> 2, tg = lane & 3;
    const int m0 = wid * 16;

    const int la_row = lane & 15, la_chunk = (lane >> 4) * 4;

    const uint32_t qs_base = (uint32_t)__cvta_generic_to_shared(Qs);
    const uint32_t ks_base = (uint32_t)__cvta_generic_to_shared(Ks);
    const uint32_t ps_base = (uint32_t)__cvta_generic_to_shared(Ps);
    const uint32_t vs_base = (uint32_t)__cvta_generic_to_shared(Vs);
    const uint32_t ms_base = (uint32_t)__cvta_generic_to_shared(Ms);

    const int bid = blockIdx.x;
    const int qt = bid & 7;
    const int h  = (bid >> 3) & 15;
    const int b  = bid >> 7;

    const uint32_t* qp = qvh + ((size_t)(b * S_LEN) + qt * 128) * 1024 + h * 32;
    const uint32_t* vp = qvh + ((size_t)(b * S_LEN)) * 1024 + 512 + h * 32;
    const uint32_t* kp = kh  + ((size_t)(b * S_LEN)) * 512 + h * 32;
    const float*    mp = mask + b * S_LEN;

    auto load_tile = [&](int ktn, int bb) {
        #pragma unroll
        for (int i = 0; i < 2; i++) {
            int f = tid + 256 * i;
            int row = f >> 3, w4 = (f & 7) * 4;
            int key = (ktn << 6) + row;
            CP_ASYNC16(ks_base + ((bb * 64 + row) * SQH + w4) * 4,
                       kp + (size_t)key * 512 + w4);
            CP_ASYNC16(vs_base + ((bb * 64 + row) * SQH + w4) * 4,
                       vp + (size_t)key * 1024 + w4);
        }
        if (tid < 16)
            CP_ASYNC16(ms_base + (bb * 64 + tid * 4) * 4, mp + (ktn << 6) + tid * 4);
    };

    load_tile(0, 0);
    CP_COMMIT();
    #pragma unroll
    for (int i = 0; i < 4; i++) {
        int f = tid + 256 * i;
        int row = f >> 3, w4 = (f & 7) * 4;
        uint4 u = *(const uint4*)(qp + (size_t)row * 1024 + w4);
        *(uint4*)&Qs[row * SQH + w4] = u;
    }

    float m_i[2] = {-INFINITY, -INFINITY}, l_i[2] = {0.0f, 0.0f};
    float oa[8][4];
    #pragma unroll
    for (int nt = 0; nt < 8; nt++)
        #pragma unroll
        for (int i = 0; i < 4; i++) oa[nt][i] = 0.0f;

    CP_WAIT0();
    __syncthreads();

    int buf = 0;
    const int NT = S_LEN / 64;
    for (int kt = 0; kt < NT; ++kt) {
        if (kt + 1 < NT) {
            load_tile(kt + 1, buf ^ 1);
            CP_COMMIT();
        }

        const uint32_t ksb = ks_base + (buf * 64 * SQH) * 4;
        const uint32_t vsb = vs_base + (buf * 64 * SQH) * 4;
        const float*   msb = Ms + buf * 64;

        // ---- S = Q K^T ----
        float sacc[8][4];
        #pragma unroll
        for (int nt = 0; nt < 8; nt++)
            #pragma unroll
            for (int i = 0; i < 4; i++) sacc[nt][i] = 0.0f;

        #pragma unroll
        for (int ks = 0; ks < 4; ++ks) {
            const int kb = ks * 8;
            uint32_t af[4];
            ldsm_x4(af, qs_base + ((m0 + la_row) * SQH + kb + la_chunk) * 4);
            #pragma unroll
            for (int np = 0; np < 4; ++np) {
                uint32_t bq[4];
                ldsm_x4(bq, ksb + ((np * 16 + la_row) * SQH + kb + la_chunk) * 4);
                mma16f(sacc[2 * np + 0], af, bq[0], bq[2]);
                mma16f(sacc[2 * np + 1], af, bq[1], bq[3]);
            }
        }

        // ---- online softmax ----
        #pragma unroll
        for (int rr = 0; rr < 2; ++rr) {
            float mx = -INFINITY;
            #pragma unroll
            for (int nt = 0; nt < 8; nt++) {
                const int c0 = nt * 8 + 2 * tg;
                float s0 = (sacc[nt][rr * 2 + 0] + msb[c0]) * 0.125f;
                float s1 = (sacc[nt][rr * 2 + 1] + msb[c0 + 1]) * 0.125f;
                sacc[nt][rr * 2 + 0] = s0;
                sacc[nt][rr * 2 + 1] = s1;
                mx = fmaxf(mx, fmaxf(s0, s1));
            }
            mx = fmaxf(mx, __shfl_xor_sync(0xffffffffu, mx, 1));
            mx = fmaxf(mx, __shfl_xor_sync(0xffffffffu, mx, 2));
            const float mnew = fmaxf(m_i[rr], mx);
            const float alpha = __expf(m_i[rr] - mnew);
            float rs = 0.0f;
            const int row = m0 + g + rr * 8;
            #pragma unroll
            for (int nt = 0; nt < 8; nt++) {
                float p0 = __expf(sacc[nt][rr * 2 + 0] - mnew);
                float p1 = __expf(sacc[nt][rr * 2 + 1] - mnew);
                rs += p0 + p1;
                Ps[row * SQH + nt * 4 + tg] = pack_h2(p0, p1);
            }
            rs += __shfl_xor_sync(0xffffffffu, rs, 1);
            rs += __shfl_xor_sync(0xffffffffu, rs, 2);
            l_i[rr] = l_i[rr] * alpha + rs;
            m_i[rr] = mnew;
            #pragma unroll
            for (int nt = 0; nt < 8; nt++) {
                oa[nt][rr * 2 + 0] *= alpha;
                oa[nt][rr * 2 + 1] *= alpha;
            }
        }
        __syncwarp();   // P rows are warp-private

        // ---- O += P V ----
        #pragma unroll
        for (int ks = 0; ks < 4; ++ks) {
            const int kb = ks * 8;
            uint32_t ap[4];
            ldsm_x4(ap, ps_base + ((m0 + la_row) * SQH + kb + la_chunk) * 4);
            #pragma unroll
            for (int np = 0; np < 4; ++np) {
                uint32_t bv[4];
                ldsm_x4_trans(bv, vsb +
                    ((ks * 16 + la_row) * SQH + (2 * np + (lane >> 4)) * 4) * 4);
                mma16f(oa[2 * np + 0], ap, bv[0], bv[1]);
                mma16f(oa[2 * np + 1], ap, bv[2], bv[3]);
            }
        }

        if (kt + 1 < NT) CP_WAIT0();
        __syncthreads();
        buf ^= 1;
    }

    // ---- epilogue: packed fp16 output [row][kp] for the proj GEMM ----
    #pragma unroll
    for (int rr = 0; rr < 2; ++rr) {
        const float inv = 1.0f / l_i[rr];
        const int srow = qt * 128 + m0 + g + rr * 8;
        uint32_t* op = outp + ((size_t)(b * S_LEN + srow)) * 512 + h * 32;
        #pragma unroll
        for (int nt = 0; nt < 8; nt++)
            op[nt * 4 + tg] = pack_h2(oa[nt][rr * 2 + 0] * inv, oa[nt][rr * 2 + 1] * inv);
    }
}

// ---------------- launch ----------------
extern "C" void kernel_launch(void* const* d_in, const int* in_sizes, int n_in,
                              void* d_out, int out_size)
{
    const float* hidden = (const float*)d_in[0];
    const float* mask   = (const float*)d_in[1];
    const float* w_attn = (const float*)d_in[2];
    const float* b_attn = (const float*)d_in[3];
    const float* w_proj = (const float*)d_in[4];
    const float* b_proj = (const float*)d_in[5];
    float* out = (float*)d_out;

    uint32_t *hf16, *hbh, *hbl, *qvh, *kh, *oh, *wkh, *wkl, *wqv, *wp;
    cudaGetSymbolAddress((void**)&hf16, g_hf16);
    cudaGetSymbolAddress((void**)&hbh,  g_hbh);
    cudaGetSymbolAddress((void**)&hbl,  g_hbl);
    cudaGetSymbolAddress((void**)&qvh,  g_qvh);
    cudaGetSymbolAddress((void**)&kh,   g_kh);
    cudaGetSymbolAddress((void**)&oh,   g_oh);
    cudaGetSymbolAddress((void**)&wkh,  g_wkh);
    cudaGetSymbolAddress((void**)&wkl,  g_wkl);
    cudaGetSymbolAddress((void**)&wqv,  g_wqv);
    cudaGetSymbolAddress((void**)&wp,   g_wp);

    const int att_smem = ATT_FLOATS * (int)sizeof(float);
    cudaFuncSetAttribute(attn_f16,
                         cudaFuncAttributeMaxDynamicSharedMemorySize, att_smem);
    cudaFuncSetAttribute(gemm_qvk,
                         cudaFuncAttributeMaxDynamicSharedMemorySize, QK_SMEM_BYTES);
    cudaFuncSetAttribute(gemm_proj,
                         cudaFuncAttributeMaxDynamicSharedMemorySize, QK_SMEM_BYTES);

    // 0) fused prep: hidden packs + all weight packs
    prep_all<<<16384, 256>>>(hidden, w_attn, w_proj,
                             hf16, hbh, hbl, wkh, wkl, wqv, wp);

    // 1+2) fused QV (fp16) + K (bf16x3, fused KIVI quant) GEMMs: 768 blocks
    gemm_qvk<<<768, 256, QK_SMEM_BYTES>>>(hf16, hbh, hbl, wqv, wkh, wkl,
                                          b_attn, qvh, kh);

    // 3) attention (cp.async double-buffered KV)
    attn_f16<<<BATCH * NH * (S_LEN / 128), 256, att_smem>>>(qvh, kh, mask, oh);

    // 4) out projection, fp16, fp32 output
    dim3 gp(EMB / 128, NROWS / 128);
    gemm_proj<<<gp, 256, QK_SMEM_BYTES>>>(oh, wp, b_proj, out);
}

// round 17
// speedup vs baseline: 1.0895x; 1.0252x over previous
#include <cuda_runtime.h>
#include <cuda_bf16.h>
#include <cuda_fp16.h>
#include <math.h>
#include <stdint.h>

#define BATCH 4
#define S_LEN 1024
#define EMB   1024
#define NH    16
#define HD    64
#define NROWS (BATCH * S_LEN)

// ---------------- scratch (no allocations allowed) ----------------
__device__ uint32_t g_hf16[NROWS * 512];        // hidden fp16 pairs [m][kp]
__device__ uint32_t g_hbh [NROWS * 512];        // hidden bf16 hi    [m][kp]
__device__ uint32_t g_hbl [NROWS * 512];        // hidden bf16 lo    [m][kp]
__device__ uint32_t g_qvh [NROWS * 1024];       // Q|V fp16 pairs: [row][kp], Q kp<512, V kp>=512
__device__ uint32_t g_kh  [NROWS * 512];        // K quantized fp16 pairs [row][kp]
__device__ uint32_t g_oh  [NROWS * 512];        // attention out fp16 pairs [row][kp]
__device__ uint32_t g_wkh [EMB * 512];          // Wk bf16 hi, [n][kp]
__device__ uint32_t g_wkl [EMB * 512];          // Wk bf16 lo, [n][kp]
__device__ uint32_t g_wqv [2048 * 512];         // Wq|Wv fp16, [n][kp]
__device__ uint32_t g_wp  [EMB * 512];          // Wproj fp16, [n][kp]

// ---------------- helpers ----------------
__device__ __forceinline__ void mma16bf(float* d, const uint32_t* a, uint32_t b0, uint32_t b1) {
    asm volatile(
        "mma.sync.aligned.m16n8k16.row.col.f32.bf16.bf16.f32 "
        "{%0,%1,%2,%3}, {%4,%5,%6,%7}, {%8,%9}, {%0,%1,%2,%3};"
        : "+f"(d[0]), "+f"(d[1]), "+f"(d[2]), "+f"(d[3])
        : "r"(a[0]), "r"(a[1]), "r"(a[2]), "r"(a[3]), "r"(b0), "r"(b1));
}

__device__ __forceinline__ void mma16f(float* d, const uint32_t* a, uint32_t b0, uint32_t b1) {
    asm volatile(
        "mma.sync.aligned.m16n8k16.row.col.f32.f16.f16.f32 "
        "{%0,%1,%2,%3}, {%4,%5,%6,%7}, {%8,%9}, {%0,%1,%2,%3};"
        : "+f"(d[0]), "+f"(d[1]), "+f"(d[2]), "+f"(d[3])
        : "r"(a[0]), "r"(a[1]), "r"(a[2]), "r"(a[3]), "r"(b0), "r"(b1));
}

__device__ __forceinline__ void ldsm_x4(uint32_t* r, uint32_t addr) {
    asm volatile("ldmatrix.sync.aligned.m8n8.x4.shared.b16 {%0,%1,%2,%3}, [%4];"
        : "=r"(r[0]), "=r"(r[1]), "=r"(r[2]), "=r"(r[3]) : "r"(addr));
}

__device__ __forceinline__ void ldsm_x4_trans(uint32_t* r, uint32_t addr) {
    asm volatile("ldmatrix.sync.aligned.m8n8.x4.trans.shared.b16 {%0,%1,%2,%3}, [%4];"
        : "=r"(r[0]), "=r"(r[1]), "=r"(r[2]), "=r"(r[3]) : "r"(addr));
}

#define CP_ASYNC16(saddr, gptr) \
    asm volatile("cp.async.cg.shared.global [%0], [%1], 16;" \
        :: "r"(saddr), "l"(gptr) : "memory")
#define CP_COMMIT() asm volatile("cp.async.commit_group;" ::: "memory")
#define CP_WAIT0()  asm volatile("cp.async.wait_group 0;" ::: "memory")

__device__ __forceinline__ uint32_t pack_bf2(float x0, float x1) {
    __nv_bfloat162 p = __floats2bfloat162_rn(x0, x1);
    return *(uint32_t*)&p;
}

__device__ __forceinline__ uint32_t pack_h2(float x0, float x1) {
    __half2 p = __floats2half2_rn(x0, x1);
    return *(uint32_t*)&p;
}

__device__ __forceinline__ void split_bf(float x, float& h, float& l) {
    __nv_bfloat16 hb = __float2bfloat16_rn(x);
    h = __bfloat162float(hb);
    l = x - h;
}

__device__ __forceinline__ uint32_t kivi2(float v0, float v1, float ma) {
    float scale = ma * (1.0f / 1.5f);
    float safe = (scale == 0.0f) ? 1.0f : scale;
    float c0 = fminf(fmaxf(rintf(v0 / safe + 1.5f), 0.0f), 3.0f);
    float c1 = fminf(fmaxf(rintf(v1 / safe + 1.5f), 0.0f), 3.0f);
    return pack_h2((c0 - 1.5f) * scale, (c1 - 1.5f) * scale);
}

// ---------------- fused prep: hidden packs + all weight packs ----------------
__global__ __launch_bounds__(256) void prep_all(
    const float* __restrict__ hid, const float* __restrict__ wa,
    const float* __restrict__ wpj,
    uint32_t* __restrict__ hf, uint32_t* __restrict__ hh, uint32_t* __restrict__ hl,
    uint32_t* __restrict__ wkh, uint32_t* __restrict__ wkl,
    uint32_t* __restrict__ wqv, uint32_t* __restrict__ wp)
{
    int bidx = blockIdx.x;
    if (bidx < 8192) {
        int idx = bidx * 256 + threadIdx.x;
        int kp = idx & 511;
        int m  = idx >> 9;
        float2 v = *(const float2*)(hid + (size_t)m * EMB + 2 * kp);
        hf[idx] = pack_h2(v.x, v.y);
        float h0, l0, h1, l1;
        split_bf(v.x, h0, l0);
        split_bf(v.y, h1, l1);
        hh[idx] = pack_bf2(h0, h1);
        hl[idx] = pack_bf2(l0, l1);
    } else if (bidx < 10240) {
        int idx = (bidx - 8192) * 256 + threadIdx.x;
        int n  = idx & 1023;
        int kp = idx >> 10;
        float x0 = wa[(size_t)(2 * kp)     * (3 * EMB) + EMB + n];
        float x1 = wa[(size_t)(2 * kp + 1) * (3 * EMB) + EMB + n];
        float h0, l0, h1, l1;
        split_bf(x0, h0, l0);
        split_bf(x1, h1, l1);
        wkh[(size_t)n * 512 + kp] = pack_bf2(h0, h1);
        wkl[(size_t)n * 512 + kp] = pack_bf2(l0, l1);
    } else if (bidx < 14336) {
        int idx = (bidx - 10240) * 256 + threadIdx.x;
        int n  = idx & 2047;
        int kp = idx >> 11;
        int col = n + ((n >= 1024) ? 1024 : 0);
        float x0 = wa[(size_t)(2 * kp)     * (3 * EMB) + col];
        float x1 = wa[(size_t)(2 * kp + 1) * (3 * EMB) + col];
        wqv[(size_t)n * 512 + kp] = pack_h2(x0, x1);
    } else {
        int idx = (bidx - 14336) * 256 + threadIdx.x;
        int n  = idx & 1023;
        int kp = idx >> 10;
        float x0 = wpj[(size_t)(2 * kp)     * EMB + n];
        float x1 = wpj[(size_t)(2 * kp + 1) * EMB + n];
        wp[(size_t)n * 512 + kp] = pack_h2(x0, x1);
    }
}

// ---------------- tile constants ----------------
#define GF_S 20
#define GF_BUF (128 * GF_S)
#define G3_S 12
#define G3_BUF (128 * G3_S)
#define QK_SMEM_BYTES (8 * G3_BUF * 4)   // 48KB (>= fp16 path's 40KB)

// ---------------- fp16 GEMM body (cp.async, BK=32) ----------------
__device__ __forceinline__ void gemm_f16_body(
    uint32_t* sm, int bx, int by,
    const uint32_t* __restrict__ Apk, const uint32_t* __restrict__ Bp,
    const float* __restrict__ bias, float* __restrict__ C,
    uint32_t* __restrict__ Cp, int ldc, int K, int nsplit, int gap, int pack_out)
{
    uint32_t* As = sm;                  // [2][GF_BUF]
    uint32_t* Bs = As + 2 * GF_BUF;

    const int tid = threadIdx.x;
    const int bcol = bx * 128 + ((bx >= nsplit) ? gap : 0);
    const int lane = tid & 31, wid = tid >> 5;
    const int g = lane >> 2, tg = lane & 3;
    const int wm = (wid >> 2) * 64, wn = (wid & 3) * 32;

    const int la_row = lane & 15, la_chunk = (lane >> 4) * 4;

    const uint32_t as_base = (uint32_t)__cvta_generic_to_shared(As);
    const uint32_t bs_base = (uint32_t)__cvta_generic_to_shared(Bs);

    const int arow = tid >> 1, akp = (tid & 1) * 8;
    const uint32_t* App = Apk + (size_t)(by * 128 + arow) * 512 + akp;
    const uint32_t* Bpp = Bp  + (size_t)(bx * 128 + arow) * 512 + akp;

    auto load_tile = [&](int t, int bb) {
        const uint32_t da = as_base + (bb * GF_BUF + arow * GF_S + akp) * 4;
        const uint32_t db = bs_base + (bb * GF_BUF + arow * GF_S + akp) * 4;
        CP_ASYNC16(da,      App + t * 16);
        CP_ASYNC16(da + 16, App + t * 16 + 4);
        CP_ASYNC16(db,      Bpp + t * 16);
        CP_ASYNC16(db + 16, Bpp + t * 16 + 4);
    };

    float acc[4][4][4];
    #pragma unroll
    for (int mt = 0; mt < 4; mt++)
        #pragma unroll
        for (int nt = 0; nt < 4; nt++)
            #pragma unroll
            for (int i = 0; i < 4; i++) acc[mt][nt][i] = 0.0f;

    load_tile(0, 0);
    CP_COMMIT();
    CP_WAIT0();
    __syncthreads();

    const int ntiles = K >> 5;
    int buf = 0;
    for (int t = 0; t < ntiles; ++t) {
        if (t + 1 < ntiles) {
            load_tile(t + 1, buf ^ 1);
            CP_COMMIT();
        }

        const uint32_t as0 = as_base + (buf * GF_BUF) * 4;
        const uint32_t bs0 = bs_base + (buf * GF_BUF) * 4;

        #pragma unroll
        for (int ks = 0; ks < 2; ++ks) {
            const int kb = ks * 8;
            uint32_t af[4][4], bq[2][4];
            #pragma unroll
            for (int mt = 0; mt < 4; mt++)
                ldsm_x4(af[mt], as0 + ((wm + mt * 16 + la_row) * GF_S + kb + la_chunk) * 4);
            #pragma unroll
            for (int np = 0; np < 2; np++)
                ldsm_x4(bq[np], bs0 + ((wn + np * 16 + la_row) * GF_S + kb + la_chunk) * 4);
            #pragma unroll
            for (int mt = 0; mt < 4; mt++)
                #pragma unroll
                for (int np = 0; np < 2; np++) {
                    mma16f(acc[mt][2 * np + 0], af[mt], bq[np][0], bq[np][2]);
                    mma16f(acc[mt][2 * np + 1], af[mt], bq[np][1], bq[np][3]);
                }
        }

        if (t + 1 < ntiles) CP_WAIT0();
        __syncthreads();
        buf ^= 1;
    }

    #pragma unroll
    for (int mt = 0; mt < 4; mt++) {
        #pragma unroll
        for (int nt = 0; nt < 4; nt++) {
            const int col = bcol + wn + nt * 8 + 2 * tg;
            const float bv0 = bias[col], bv1 = bias[col + 1];
            const int row0 = by * 128 + wm + mt * 16 + g;
            float o00 = acc[mt][nt][0] + bv0, o01 = acc[mt][nt][1] + bv1;
            float o10 = acc[mt][nt][2] + bv0, o11 = acc[mt][nt][3] + bv1;
            if (pack_out) {
                const int kp = (col >= 2048) ? (512 + ((col - 2048) >> 1)) : (col >> 1);
                Cp[(size_t)row0 * 1024 + kp]       = pack_h2(o00, o01);
                Cp[(size_t)(row0 + 8) * 1024 + kp] = pack_h2(o10, o11);
            } else {
                *(float2*)(C + (size_t)row0 * ldc + col)       = make_float2(o00, o01);
                *(float2*)(C + (size_t)(row0 + 8) * ldc + col) = make_float2(o10, o11);
            }
        }
    }
}

// ---------------- bf16x3 K-GEMM body (BK=16, reg prefetch, fused quant) ----------------
__device__ __forceinline__ void gemm_bf16k_body(
    uint32_t* sm, int bx, int by,
    const uint32_t* __restrict__ Ahg, const uint32_t* __restrict__ Alg,
    const uint32_t* __restrict__ Bhg, const uint32_t* __restrict__ Blg,
    const float* __restrict__ bias, uint32_t* __restrict__ Kp, int K)
{
    uint32_t* Ah = sm;
    uint32_t* Al = Ah + 2 * G3_BUF;
    uint32_t* Bh = Al + 2 * G3_BUF;
    uint32_t* Bl = Bh + 2 * G3_BUF;

    const int tid = threadIdx.x;
    const int lane = tid & 31, wid = tid >> 5;
    const int g = lane >> 2, tg = lane & 3;
    const int wm = (wid >> 2) * 64, wn = (wid & 3) * 32;

    const int la_row = lane & 15, la_chunk = (lane >> 4) * 4;

    const uint32_t ah_base = (uint32_t)__cvta_generic_to_shared(Ah);
    const uint32_t al_base = (uint32_t)__cvta_generic_to_shared(Al);
    const uint32_t bh_base = (uint32_t)__cvta_generic_to_shared(Bh);
    const uint32_t bl_base = (uint32_t)__cvta_generic_to_shared(Bl);

    const int arow = tid >> 1, akp = (tid & 1) * 4;
    const uint32_t* Ahp = Ahg + (size_t)(by * 128 + arow) * 512 + akp;
    const uint32_t* Alp = Alg + (size_t)(by * 128 + arow) * 512 + akp;
    const uint32_t* Bhp = Bhg + (size_t)(bx * 128 + arow) * 512 + akp;
    const uint32_t* Blp = Blg + (size_t)(bx * 128 + arow) * 512 + akp;

    float acc[4][4][4];
    #pragma unroll
    for (int mt = 0; mt < 4; mt++)
        #pragma unroll
        for (int nt = 0; nt < 4; nt++)
            #pragma unroll
            for (int i = 0; i < 4; i++) acc[mt][nt][i] = 0.0f;

    uint4 pah = *(const uint4*)(Ahp);
    uint4 pal = *(const uint4*)(Alp);
    uint4 pbh = *(const uint4*)(Bhp);
    uint4 pbl = *(const uint4*)(Blp);

    const int ntiles = K >> 4;
    int buf = 0;
    {
        *(uint4*)&Ah[arow * G3_S + akp] = pah;
        *(uint4*)&Al[arow * G3_S + akp] = pal;
        *(uint4*)&Bh[arow * G3_S + akp] = pbh;
        *(uint4*)&Bl[arow * G3_S + akp] = pbl;
    }
    __syncthreads();

    for (int t = 0; t < ntiles; ++t) {
        if (t + 1 < ntiles) {
            pah = *(const uint4*)(Ahp + (t + 1) * 8);
            pal = *(const uint4*)(Alp + (t + 1) * 8);
            pbh = *(const uint4*)(Bhp + (t + 1) * 8);
            pbl = *(const uint4*)(Blp + (t + 1) * 8);
        }

        const uint32_t ah0 = ah_base + (buf * G3_BUF) * 4;
        const uint32_t al0 = al_base + (buf * G3_BUF) * 4;
        const uint32_t bh0 = bh_base + (buf * G3_BUF) * 4;
        const uint32_t bl0 = bl_base + (buf * G3_BUF) * 4;

        uint32_t afh[4][4], afl[4][4], bqh[2][4], bql[2][4];
        #pragma unroll
        for (int mt = 0; mt < 4; mt++) {
            const uint32_t off = ((wm + mt * 16 + la_row) * G3_S + la_chunk) * 4;
            ldsm_x4(afh[mt], ah0 + off);
            ldsm_x4(afl[mt], al0 + off);
        }
        #pragma unroll
        for (int np = 0; np < 2; np++) {
            const uint32_t off = ((wn + np * 16 + la_row) * G3_S + la_chunk) * 4;
            ldsm_x4(bqh[np], bh0 + off);
            ldsm_x4(bql[np], bl0 + off);
        }
        #pragma unroll
        for (int mt = 0; mt < 4; mt++)
            #pragma unroll
            for (int np = 0; np < 2; np++) {
                float* a0 = acc[mt][2 * np + 0];
                float* a1 = acc[mt][2 * np + 1];
                mma16bf(a0, afh[mt], bqh[np][0], bqh[np][2]);
                mma16bf(a0, afh[mt], bql[np][0], bql[np][2]);
                mma16bf(a0, afl[mt], bqh[np][0], bqh[np][2]);
                mma16bf(a1, afh[mt], bqh[np][1], bqh[np][3]);
                mma16bf(a1, afh[mt], bql[np][1], bql[np][3]);
                mma16bf(a1, afl[mt], bqh[np][1], bqh[np][3]);
            }

        if (t + 1 < ntiles) {
            const int nb = buf ^ 1;
            __syncthreads();
            *(uint4*)&Ah[nb * G3_BUF + arow * G3_S + akp] = pah;
            *(uint4*)&Al[nb * G3_BUF + arow * G3_S + akp] = pal;
            *(uint4*)&Bh[nb * G3_BUF + arow * G3_S + akp] = pbh;
            *(uint4*)&Bl[nb * G3_BUF + arow * G3_S + akp] = pbl;
            __syncthreads();
            buf = nb;
        }
    }

    // epilogue: bias + KIVI 2-bit quant (group = tg-pair) + pack fp16
    #pragma unroll
    for (int mt = 0; mt < 4; mt++) {
        #pragma unroll
        for (int nt = 0; nt < 4; nt++) {
            const int col = bx * 128 + wn + nt * 8 + 2 * tg;
            const float bv0 = bias[col], bv1 = bias[col + 1];
            const int row0 = by * 128 + wm + mt * 16 + g;
            float v00 = acc[mt][nt][0] + bv0, v01 = acc[mt][nt][1] + bv1;
            float v10 = acc[mt][nt][2] + bv0, v11 = acc[mt][nt][3] + bv1;
            float ma0 = fmaxf(fabsf(v00), fabsf(v01));
            float ma1 = fmaxf(fabsf(v10), fabsf(v11));
            ma0 = fmaxf(ma0, __shfl_xor_sync(0xffffffffu, ma0, 1));
            ma1 = fmaxf(ma1, __shfl_xor_sync(0xffffffffu, ma1, 1));
            const int kp = col >> 1;
            Kp[(size_t)row0 * 512 + kp]       = kivi2(v00, v01, ma0);
            Kp[(size_t)(row0 + 8) * 512 + kp] = kivi2(v10, v11, ma1);
        }
    }
}

// ---------------- fused QV + K GEMM launch: 768 blocks ----------------
__global__ __launch_bounds__(256, 2) void gemm_qvk(
    const uint32_t* __restrict__ hf16,
    const uint32_t* __restrict__ hbh, const uint32_t* __restrict__ hbl,
    const uint32_t* __restrict__ wqv,
    const uint32_t* __restrict__ wkh, const uint32_t* __restrict__ wkl,
    const float* __restrict__ b_attn,
    uint32_t* __restrict__ qvh, uint32_t* __restrict__ kh)
{
    extern __shared__ uint32_t sm[];
    const int bid = blockIdx.x;
    if (bid < 512) {
        gemm_f16_body(sm, bid & 15, bid >> 4, hf16, wqv, b_attn,
                      nullptr, qvh, 0, EMB, 8, 1024, 1);
    } else {
        const int r = bid - 512;
        gemm_bf16k_body(sm, r & 7, r >> 3, hbh, hbl, wkh, wkl,
                        b_attn + EMB, kh, EMB);
    }
}

// ---------------- proj GEMM (standalone, fp32 out) ----------------
__global__ __launch_bounds__(256, 2) void gemm_proj(
    const uint32_t* __restrict__ oh, const uint32_t* __restrict__ wp,
    const float* __restrict__ b_proj, float* __restrict__ out)
{
    extern __shared__ uint32_t sm[];
    gemm_f16_body(sm, blockIdx.x, blockIdx.y, oh, wp, b_proj,
                  out, nullptr, EMB, EMB, 16, 0, 0);
}

// ---------------- Flash attention: cp.async KV pipeline, register-resident P ----------------
#define SQH 36
#define ATT_FLOATS (128 * SQH + 2 * 64 * SQH + 2 * 64 * SQH + 2 * 64)

__global__ __launch_bounds__(256, 2) void attn_f16(
    const uint32_t* __restrict__ qvh, const uint32_t* __restrict__ kh,
    const float* __restrict__ mask, uint32_t* __restrict__ outp)
{
    extern __shared__ uint32_t smu[];
    uint32_t* Qs = smu;                       // [128][36]
    uint32_t* Ks = Qs + 128 * SQH;            // [2][64][36]
    uint32_t* Vs = Ks + 2 * 64 * SQH;         // [2][64][36]
    float*    Ms = (float*)(Vs + 2 * 64 * SQH);  // [2][64]

    const int tid = threadIdx.x, lane = tid & 31, wid = tid >> 5;
    const int g = lane >> 2, tg = lane & 3;
    const int m0 = wid * 16;

    const int la_row = lane & 15, la_chunk = (lane >> 4) * 4;

    const uint32_t qs_base = (uint32_t)__cvta_generic_to_shared(Qs);
    const uint32_t ks_base = (uint32_t)__cvta_generic_to_shared(Ks);
    const uint32_t vs_base = (uint32_t)__cvta_generic_to_shared(Vs);
    const uint32_t ms_base = (uint32_t)__cvta_generic_to_shared(Ms);

    const int bid = blockIdx.x;
    const int qt = bid & 7;
    const int h  = (bid >> 3) & 15;
    const int b  = bid >> 7;

    const uint32_t* qp = qvh + ((size_t)(b * S_LEN) + qt * 128) * 1024 + h * 32;
    const uint32_t* vp = qvh + ((size_t)(b * S_LEN)) * 1024 + 512 + h * 32;
    const uint32_t* kp = kh  + ((size_t)(b * S_LEN)) * 512 + h * 32;
    const float*    mp = mask + b * S_LEN;

    auto load_tile = [&](int ktn, int bb) {
        #pragma unroll
        for (int i = 0; i < 2; i++) {
            int f = tid + 256 * i;
            int row = f >> 3, w4 = (f & 7) * 4;
            int key = (ktn << 6) + row;
            CP_ASYNC16(ks_base + ((bb * 64 + row) * SQH + w4) * 4,
                       kp + (size_t)key * 512 + w4);
            CP_ASYNC16(vs_base + ((bb * 64 + row) * SQH + w4) * 4,
                       vp + (size_t)key * 1024 + w4);
        }
        if (tid < 16)
            CP_ASYNC16(ms_base + (bb * 64 + tid * 4) * 4, mp + (ktn << 6) + tid * 4);
    };

    load_tile(0, 0);
    CP_COMMIT();
    #pragma unroll
    for (int i = 0; i < 4; i++) {
        int f = tid + 256 * i;
        int row = f >> 3, w4 = (f & 7) * 4;
        uint4 u = *(const uint4*)(qp + (size_t)row * 1024 + w4);
        *(uint4*)&Qs[row * SQH + w4] = u;
    }

    float m_i[2] = {-INFINITY, -INFINITY}, l_i[2] = {0.0f, 0.0f};
    float oa[8][4];
    #pragma unroll
    for (int nt = 0; nt < 8; nt++)
        #pragma unroll
        for (int i = 0; i < 4; i++) oa[nt][i] = 0.0f;

    CP_WAIT0();
    __syncthreads();

    int buf = 0;
    const int NT = S_LEN / 64;
    for (int kt = 0; kt < NT; ++kt) {
        if (kt + 1 < NT) {
            load_tile(kt + 1, buf ^ 1);
            CP_COMMIT();
        }

        const uint32_t ksb = ks_base + (buf * 64 * SQH) * 4;
        const uint32_t vsb = vs_base + (buf * 64 * SQH) * 4;
        const float*   msb = Ms + buf * 64;

        // ---- S = Q K^T ----
        float sacc[8][4];
        #pragma unroll
        for (int nt = 0; nt < 8; nt++)
            #pragma unroll
            for (int i = 0; i < 4; i++) sacc[nt][i] = 0.0f;

        #pragma unroll
        for (int ks = 0; ks < 4; ++ks) {
            const int kb = ks * 8;
            uint32_t af[4];
            ldsm_x4(af, qs_base + ((m0 + la_row) * SQH + kb + la_chunk) * 4);
            #pragma unroll
            for (int np = 0; np < 4; ++np) {
                uint32_t bq[4];
                ldsm_x4(bq, ksb + ((np * 16 + la_row) * SQH + kb + la_chunk) * 4);
                mma16f(sacc[2 * np + 0], af, bq[0], bq[2]);
                mma16f(sacc[2 * np + 1], af, bq[1], bq[3]);
            }
        }

        // ---- online softmax; P packed straight into PV A-fragments ----
        // pfrag[ks] = A-fragment for k16-step ks:
        //   [0]=row g keys 16ks+2tg.., [1]=row g+8 same, [2]/[3]= +8 pair
        uint32_t pfrag[4][4];
        #pragma unroll
        for (int rr = 0; rr < 2; ++rr) {
            float mx = -INFINITY;
            #pragma unroll
            for (int nt = 0; nt < 8; nt++) {
                const int c0 = nt * 8 + 2 * tg;
                float s0 = (sacc[nt][rr * 2 + 0] + msb[c0]) * 0.125f;
                float s1 = (sacc[nt][rr * 2 + 1] + msb[c0 + 1]) * 0.125f;
                sacc[nt][rr * 2 + 0] = s0;
                sacc[nt][rr * 2 + 1] = s1;
                mx = fmaxf(mx, fmaxf(s0, s1));
            }
            mx = fmaxf(mx, __shfl_xor_sync(0xffffffffu, mx, 1));
            mx = fmaxf(mx, __shfl_xor_sync(0xffffffffu, mx, 2));
            const float mnew = fmaxf(m_i[rr], mx);
            const float alpha = __expf(m_i[rr] - mnew);
            float rs = 0.0f;
            #pragma unroll
            for (int nt = 0; nt < 8; nt++) {
                float p0 = __expf(sacc[nt][rr * 2 + 0] - mnew);
                float p1 = __expf(sacc[nt][rr * 2 + 1] - mnew);
                rs += p0 + p1;
                pfrag[nt >> 1][(nt & 1) * 2 + rr] = pack_h2(p0, p1);
            }
            rs += __shfl_xor_sync(0xffffffffu, rs, 1);
            rs += __shfl_xor_sync(0xffffffffu, rs, 2);
            l_i[rr] = l_i[rr] * alpha + rs;
            m_i[rr] = mnew;
            #pragma unroll
            for (int nt = 0; nt < 8; nt++) {
                oa[nt][rr * 2 + 0] *= alpha;
                oa[nt][rr * 2 + 1] *= alpha;
            }
        }

        // ---- O += P V (A from registers, B via ldmatrix.trans) ----
        #pragma unroll
        for (int ks = 0; ks < 4; ++ks) {
            #pragma unroll
            for (int np = 0; np < 4; ++np) {
                uint32_t bv[4];
                ldsm_x4_trans(bv, vsb +
                    ((ks * 16 + la_row) * SQH + (2 * np + (lane >> 4)) * 4) * 4);
                mma16f(oa[2 * np + 0], pfrag[ks], bv[0], bv[1]);
                mma16f(oa[2 * np + 1], pfrag[ks], bv[2], bv[3]);
            }
        }

        if (kt + 1 < NT) CP_WAIT0();
        __syncthreads();
        buf ^= 1;
    }

    // ---- epilogue: packed fp16 output [row][kp] for the proj GEMM ----
    #pragma unroll
    for (int rr = 0; rr < 2; ++rr) {
        const float inv = 1.0f / l_i[rr];
        const int srow = qt * 128 + m0 + g + rr * 8;
        uint32_t* op = outp + ((size_t)(b * S_LEN + srow)) * 512 + h * 32;
        #pragma unroll
        for (int nt = 0; nt < 8; nt++)
            op[nt * 4 + tg] = pack_h2(oa[nt][rr * 2 + 0] * inv, oa[nt][rr * 2 + 1] * inv);
    }
}

// ---------------- launch ----------------
extern "C" void kernel_launch(void* const* d_in, const int* in_sizes, int n_in,
                              void* d_out, int out_size)
{
    const float* hidden = (const float*)d_in[0];
    const float* mask   = (const float*)d_in[1];
    const float* w_attn = (const float*)d_in[2];
    const float* b_attn = (const float*)d_in[3];
    const float* w_proj = (const float*)d_in[4];
    const float* b_proj = (const float*)d_in[5];
    float* out = (float*)d_out;

    uint32_t *hf16, *hbh, *hbl, *qvh, *kh, *oh, *wkh, *wkl, *wqv, *wp;
    cudaGetSymbolAddress((void**)&hf16, g_hf16);
    cudaGetSymbolAddress((void**)&hbh,  g_hbh);
    cudaGetSymbolAddress((void**)&hbl,  g_hbl);
    cudaGetSymbolAddress((void**)&qvh,  g_qvh);
    cudaGetSymbolAddress((void**)&kh,   g_kh);
    cudaGetSymbolAddress((void**)&oh,   g_oh);
    cudaGetSymbolAddress((void**)&wkh,  g_wkh);
    cudaGetSymbolAddress((void**)&wkl,  g_wkl);
    cudaGetSymbolAddress((void**)&wqv,  g_wqv);
    cudaGetSymbolAddress((void**)&wp,   g_wp);

    const int att_smem = ATT_FLOATS * (int)sizeof(float);
    cudaFuncSetAttribute(attn_f16,
                         cudaFuncAttributeMaxDynamicSharedMemorySize, att_smem);
    cudaFuncSetAttribute(gemm_qvk,
                         cudaFuncAttributeMaxDynamicSharedMemorySize, QK_SMEM_BYTES);
    cudaFuncSetAttribute(gemm_proj,
                         cudaFuncAttributeMaxDynamicSharedMemorySize, QK_SMEM_BYTES);

    // 0) fused prep: hidden packs + all weight packs
    prep_all<<<16384, 256>>>(hidden, w_attn, w_proj,
                             hf16, hbh, hbl, wkh, wkl, wqv, wp);

    // 1+2) fused QV (fp16) + K (bf16x3, fused KIVI quant) GEMMs: 768 blocks
    gemm_qvk<<<768, 256, QK_SMEM_BYTES>>>(hf16, hbh, hbl, wqv, wkh, wkl,
                                          b_attn, qvh, kh);

    // 3) attention (cp.async KV pipeline, register-resident P)
    attn_f16<<<BATCH * NH * (S_LEN / 128), 256, att_smem>>>(qvh, kh, mask, oh);

    // 4) out projection, fp16, fp32 output
    dim3 gp(EMB / 128, NROWS / 128);
    gemm_proj<<<gp, 256, QK_SMEM_BYTES>>>(oh, wp, b_proj, out);
}